// round 11
// baseline (speedup 1.0000x reference)
#include <cuda_runtime.h>
#include <cuda_bf16.h>
#include <cstdint>
#include <cstddef>

// ---------------- Problem constants ----------------
#define T_SEQ 2048
#define D_MODEL 2048
#define NH 16
#define DK 128
#define DV 128
#define CONV_W 4
#define CONV_DIM 6144          // NH*2*DK + NH*DV
#define GEN_HIDDEN 768
#define KERN_N 24576           // CONV_DIM * CONV_W
#define SK 3                   // split-K factor for GEMM2
#define SK_LEN 2048            // K per split (6144/3)

// ---------------- fp32 scratch ----------------
__device__ float g_u   [(size_t)T_SEQ * CONV_DIM];
__device__ float g_kern[(size_t)T_SEQ * KERN_N];
__device__ float g_uc  [(size_t)T_SEQ * CONV_DIM];
__device__ float g_qn  [(size_t)T_SEQ * NH * DK];
__device__ float g_kn  [(size_t)T_SEQ * NH * DK];
__device__ float g_beta[(size_t)T_SEQ * NH];
__device__ float g_g   [(size_t)T_SEQ * NH];
__device__ float g_p2  [(size_t)SK * T_SEQ * GEN_HIDDEN];   // split-K partials

// ---------------- bf16 hi/lo splits ----------------
__device__ __nv_bfloat16 g_xh [(size_t)T_SEQ * D_MODEL];
__device__ __nv_bfloat16 g_xl [(size_t)T_SEQ * D_MODEL];
__device__ __nv_bfloat16 g_uh [(size_t)T_SEQ * CONV_DIM];
__device__ __nv_bfloat16 g_ul [(size_t)T_SEQ * CONV_DIM];
__device__ __nv_bfloat16 g_hh [(size_t)T_SEQ * GEN_HIDDEN];
__device__ __nv_bfloat16 g_hl [(size_t)T_SEQ * GEN_HIDDEN];
__device__ __nv_bfloat16 g_oh [(size_t)T_SEQ * NH * DV];
__device__ __nv_bfloat16 g_ol [(size_t)T_SEQ * NH * DV];
// transposed weights [N, K]
__device__ __nv_bfloat16 g_wqh[(size_t)CONV_DIM * D_MODEL];
__device__ __nv_bfloat16 g_wql[(size_t)CONV_DIM * D_MODEL];
__device__ __nv_bfloat16 g_w1h[(size_t)GEN_HIDDEN * CONV_DIM];
__device__ __nv_bfloat16 g_w1l[(size_t)GEN_HIDDEN * CONV_DIM];
__device__ __nv_bfloat16 g_w2h[(size_t)KERN_N * GEN_HIDDEN];
__device__ __nv_bfloat16 g_w2l[(size_t)KERN_N * GEN_HIDDEN];
__device__ __nv_bfloat16 g_woh[(size_t)D_MODEL * D_MODEL];
__device__ __nv_bfloat16 g_wol[(size_t)D_MODEL * D_MODEL];

// ---------------- PTX helpers ----------------
__device__ __forceinline__ uint32_t smem_u32(const void* p) {
    uint32_t a;
    asm("{ .reg .u64 t; cvta.to.shared.u64 t, %1; cvt.u32.u64 %0, t; }" : "=r"(a) : "l"(p));
    return a;
}

#define SWZ(off) ((off) ^ (((off) >> 3) & 0x70))

#define CP_ASYNC16(dst, src) \
    asm volatile("cp.async.cg.shared.global [%0], [%1], 16;" :: "r"(dst), "l"(src) : "memory")
#define CP_COMMIT() asm volatile("cp.async.commit_group;" ::: "memory")
#define CP_WAIT1()  asm volatile("cp.async.wait_group 1;" ::: "memory")
#define CP_WAIT2()  asm volatile("cp.async.wait_group 2;" ::: "memory")

#define LDSM4(r0, r1, r2, r3, addr) \
    asm volatile("ldmatrix.sync.aligned.m8n8.x4.shared.b16 {%0,%1,%2,%3}, [%4];" \
        : "=r"(r0), "=r"(r1), "=r"(r2), "=r"(r3) : "r"(addr))

#define MMA16816(c, a, b) \
    asm volatile("mma.sync.aligned.m16n8k16.row.col.f32.bf16.bf16.f32 " \
        "{%0,%1,%2,%3}, {%4,%5,%6,%7}, {%8,%9}, {%0,%1,%2,%3};" \
        : "+f"((c)[0]), "+f"((c)[1]), "+f"((c)[2]), "+f"((c)[3]) \
        : "r"((a)[0]), "r"((a)[1]), "r"((a)[2]), "r"((a)[3]), "r"((b)[0]), "r"((b)[1]))

// ============================================================================
// mm_gemm_big: CTA 128(M) x 256(N), BK=64, 2-stage. 8 warps = 2(M) x 4(N),
// warp tile 64x64. bf16x3 compensated, fp32 accumulate.
// epi: 0 none, 1 silu, 2 +bias
// ============================================================================
#define BTILE_A 16384
#define BTILE_B 32768
#define BSTAGE  (2 * BTILE_A + 2 * BTILE_B)   // 96 KB
#define BIG_SMEM (2 * BSTAGE + 1024)

__global__ __launch_bounds__(256) void mm_gemm_big(
    const __nv_bfloat16* __restrict__ Ah, const __nv_bfloat16* __restrict__ Al,
    const __nv_bfloat16* __restrict__ Bh, const __nv_bfloat16* __restrict__ Bl,
    float* __restrict__ C, int N, int K, int epi, const float* __restrict__ bias,
    __nv_bfloat16* __restrict__ Chi, __nv_bfloat16* __restrict__ Clo)
{
    extern __shared__ char smem_raw[];
    const uint32_t sb = (smem_u32(smem_raw) + 1023u) & ~1023u;
    const int tid  = threadIdx.x;
    const int lane = tid & 31;
    const int wid  = tid >> 5;
    const int warp_m = wid & 1;
    const int warp_n = wid >> 1;
    const int mt = blockIdx.x, nt = blockIdx.y;

    const __nv_bfloat16* gpA[2] = { Ah + (size_t)mt * 128 * K,
                                    Al + (size_t)mt * 128 * K };
    const __nv_bfloat16* gpB[2] = { Bh + (size_t)nt * 256 * K,
                                    Bl + (size_t)nt * 256 * K };

    const int NC = K >> 6;
    const int ld_row = tid >> 3;
    const int ld_cc  = tid & 7;

    auto load_stage = [&](int kc, int s) {
        const uint32_t stage = sb + (uint32_t)s * BSTAGE;
        const size_t kOff = (size_t)kc * 64 + ld_cc * 8;
#pragma unroll
        for (int op = 0; op < 2; op++) {
            const __nv_bfloat16* base = gpA[op] + kOff;
#pragma unroll
            for (int i = 0; i < 4; i++) {
                const int row = ld_row + i * 32;
                uint32_t off = (uint32_t)(row * 128 + ld_cc * 16);
                CP_ASYNC16(stage + op * BTILE_A + SWZ(off), base + (size_t)row * K);
            }
        }
#pragma unroll
        for (int op = 0; op < 2; op++) {
            const __nv_bfloat16* base = gpB[op] + kOff;
#pragma unroll
            for (int i = 0; i < 8; i++) {
                const int row = ld_row + i * 32;
                uint32_t off = (uint32_t)(row * 128 + ld_cc * 16);
                CP_ASYNC16(stage + 2 * BTILE_A + op * BTILE_B + SWZ(off),
                           base + (size_t)row * K);
            }
        }
    };

    float acc[4][8][4];
#pragma unroll
    for (int m = 0; m < 4; m++)
#pragma unroll
        for (int n = 0; n < 8; n++)
#pragma unroll
            for (int j = 0; j < 4; j++) acc[m][n][j] = 0.f;

    const uint32_t aRow = (lane & 7) + ((lane >> 3) & 1) * 8;
    const uint32_t aKb  = ((lane >> 4) & 1) * 16;
    const uint32_t bRow = (lane & 7) + ((lane >> 4) & 1) * 8;
    const uint32_t bKb  = ((lane >> 3) & 1) * 16;

    load_stage(0, 0); CP_COMMIT();
    load_stage(1, 1); CP_COMMIT();

    for (int kc = 0; kc < NC; kc++) {
        CP_WAIT1();
        __syncthreads();
        const int st = kc & 1;
        const uint32_t base = sb + (uint32_t)st * BSTAGE;

#pragma unroll
        for (int ks = 0; ks < 4; ks++) {
            uint32_t a[4][2][4];
#pragma unroll
            for (int mf = 0; mf < 4; mf++) {
                uint32_t off = (uint32_t)((warp_m * 64 + mf * 16 + aRow) * 128
                                          + ks * 32 + aKb);
                uint32_t sw = SWZ(off);
                LDSM4(a[mf][0][0], a[mf][0][1], a[mf][0][2], a[mf][0][3], base + sw);
                LDSM4(a[mf][1][0], a[mf][1][1], a[mf][1][2], a[mf][1][3],
                      base + BTILE_A + sw);
            }
            uint32_t b[2][8][2];
#pragma unroll
            for (int jp = 0; jp < 4; jp++) {
                uint32_t off = (uint32_t)((warp_n * 64 + jp * 16 + bRow) * 128
                                          + ks * 32 + bKb);
                uint32_t sw = SWZ(off);
                LDSM4(b[0][2 * jp][0], b[0][2 * jp][1],
                      b[0][2 * jp + 1][0], b[0][2 * jp + 1][1],
                      base + 2 * BTILE_A + sw);
                LDSM4(b[1][2 * jp][0], b[1][2 * jp][1],
                      b[1][2 * jp + 1][0], b[1][2 * jp + 1][1],
                      base + 2 * BTILE_A + BTILE_B + sw);
            }
#pragma unroll
            for (int m = 0; m < 4; m++)
#pragma unroll
                for (int n = 0; n < 8; n++)
                    MMA16816(acc[m][n], a[m][0], b[0][n]);   // hi*hi
#pragma unroll
            for (int m = 0; m < 4; m++)
#pragma unroll
                for (int n = 0; n < 8; n++)
                    MMA16816(acc[m][n], a[m][0], b[1][n]);   // hi*lo
#pragma unroll
            for (int m = 0; m < 4; m++)
#pragma unroll
                for (int n = 0; n < 8; n++)
                    MMA16816(acc[m][n], a[m][1], b[0][n]);   // lo*hi
        }

        __syncthreads();
        if (kc + 2 < NC) load_stage(kc + 2, st);
        CP_COMMIT();
    }

    const int g  = lane >> 2;
    const int tg = lane & 3;
#pragma unroll
    for (int m = 0; m < 4; m++) {
        const int row0 = mt * 128 + warp_m * 64 + m * 16 + g;
#pragma unroll
        for (int n = 0; n < 8; n++) {
            const int col = nt * 256 + warp_n * 64 + n * 8 + tg * 2;
            float v0 = acc[m][n][0], v1 = acc[m][n][1];
            float v2 = acc[m][n][2], v3 = acc[m][n][3];
            if (epi == 1) {
                v0 = v0 / (1.f + __expf(-v0)); v1 = v1 / (1.f + __expf(-v1));
                v2 = v2 / (1.f + __expf(-v2)); v3 = v3 / (1.f + __expf(-v3));
            } else if (epi == 2) {
                float b0 = bias[col], b1 = bias[col + 1];
                v0 += b0; v1 += b1; v2 += b0; v3 += b1;
            }
            const size_t i0 = (size_t)row0 * N + col;
            const size_t i1 = (size_t)(row0 + 8) * N + col;
            if (C) {
                *(float2*)(C + i0) = make_float2(v0, v1);
                *(float2*)(C + i1) = make_float2(v2, v3);
            }
            if (Chi) {
                __nv_bfloat16 h0 = __float2bfloat16(v0), h1 = __float2bfloat16(v1);
                __nv_bfloat16 h2 = __float2bfloat16(v2), h3 = __float2bfloat16(v3);
                __nv_bfloat162 p0 = {h0, h1}, p1 = {h2, h3};
                __nv_bfloat162 q0 = {__float2bfloat16(v0 - __bfloat162float(h0)),
                                     __float2bfloat16(v1 - __bfloat162float(h1))};
                __nv_bfloat162 q1 = {__float2bfloat16(v2 - __bfloat162float(h2)),
                                     __float2bfloat16(v3 - __bfloat162float(h3))};
                *(__nv_bfloat162*)(Chi + i0) = p0;
                *(__nv_bfloat162*)(Chi + i1) = p1;
                *(__nv_bfloat162*)(Clo + i0) = q0;
                *(__nv_bfloat162*)(Clo + i1) = q1;
            }
        }
    }
}

// ============================================================================
// mm_gemm_sk: split-K GEMM2. CTA 128x128, BK=64, 3-stage, 8 warps 32x64.
// ============================================================================
#define TILE_B 16384
#define STAGE_B (4 * TILE_B)
#define SK_SMEM (3 * STAGE_B + 1024)

__global__ __launch_bounds__(256) void mm_gemm_sk(
    const __nv_bfloat16* __restrict__ Ah, const __nv_bfloat16* __restrict__ Al,
    const __nv_bfloat16* __restrict__ Bh, const __nv_bfloat16* __restrict__ Bl,
    float* __restrict__ Cpart, int N, int K)
{
    extern __shared__ char smem_raw[];
    const uint32_t sb = (smem_u32(smem_raw) + 1023u) & ~1023u;
    const int tid  = threadIdx.x;
    const int lane = tid & 31;
    const int wid  = tid >> 5;
    const int warp_m = wid & 3;
    const int warp_n = wid >> 2;
    const int mt = blockIdx.x, nt = blockIdx.y, zt = blockIdx.z;
    const int kbase = zt * SK_LEN;

    const __nv_bfloat16* gp[4] = {
        Ah + (size_t)mt * 128 * K + kbase, Al + (size_t)mt * 128 * K + kbase,
        Bh + (size_t)nt * 128 * K + kbase, Bl + (size_t)nt * 128 * K + kbase };

    const int NC = SK_LEN >> 6;   // 32
    const int ch_row[4] = { (tid + 0) >> 3, (tid + 256) >> 3,
                            (tid + 512) >> 3, (tid + 768) >> 3 };
    const int ch_cc = tid & 7;

    auto load_stage = [&](int kc, int s) {
        const uint32_t stage = sb + (uint32_t)s * STAGE_B;
        const size_t kOff = (size_t)kc * 64 + ch_cc * 8;
#pragma unroll
        for (int op = 0; op < 4; op++) {
            const __nv_bfloat16* base = gp[op] + kOff;
#pragma unroll
            for (int i = 0; i < 4; i++) {
                const int row = ch_row[i];
                uint32_t off = (uint32_t)(row * 128 + ch_cc * 16);
                CP_ASYNC16(stage + op * TILE_B + SWZ(off), base + (size_t)row * K);
            }
        }
    };

    float acc[2][8][4];
#pragma unroll
    for (int m = 0; m < 2; m++)
#pragma unroll
        for (int n = 0; n < 8; n++)
#pragma unroll
            for (int j = 0; j < 4; j++) acc[m][n][j] = 0.f;

    const uint32_t aRow = (lane & 7) + ((lane >> 3) & 1) * 8;
    const uint32_t aKb  = ((lane >> 4) & 1) * 16;
    const uint32_t bRow = (lane & 7) + ((lane >> 4) & 1) * 8;
    const uint32_t bKb  = ((lane >> 3) & 1) * 16;

    load_stage(0, 0); CP_COMMIT();
    load_stage(1, 1); CP_COMMIT();
    load_stage(2, 2); CP_COMMIT();

    for (int kc = 0; kc < NC; kc++) {
        CP_WAIT2();
        __syncthreads();
        const int st = kc % 3;
        const uint32_t base = sb + (uint32_t)st * STAGE_B;

#pragma unroll
        for (int ks = 0; ks < 4; ks++) {
            uint32_t a[2][2][4];
#pragma unroll
            for (int m = 0; m < 2; m++) {
                uint32_t off = (uint32_t)((warp_m * 32 + m * 16 + aRow) * 128
                                          + ks * 32 + aKb);
                uint32_t sw = SWZ(off);
                LDSM4(a[m][0][0], a[m][0][1], a[m][0][2], a[m][0][3], base + sw);
                LDSM4(a[m][1][0], a[m][1][1], a[m][1][2], a[m][1][3],
                      base + TILE_B + sw);
            }
            uint32_t b[2][8][2];
#pragma unroll
            for (int jp = 0; jp < 4; jp++) {
                uint32_t off = (uint32_t)((warp_n * 64 + jp * 16 + bRow) * 128
                                          + ks * 32 + bKb);
                uint32_t sw = SWZ(off);
                LDSM4(b[0][2 * jp][0], b[0][2 * jp][1],
                      b[0][2 * jp + 1][0], b[0][2 * jp + 1][1],
                      base + 2 * TILE_B + sw);
                LDSM4(b[1][2 * jp][0], b[1][2 * jp][1],
                      b[1][2 * jp + 1][0], b[1][2 * jp + 1][1],
                      base + 3 * TILE_B + sw);
            }
#pragma unroll
            for (int m = 0; m < 2; m++)
#pragma unroll
                for (int n = 0; n < 8; n++)
                    MMA16816(acc[m][n], a[m][0], b[0][n]);
#pragma unroll
            for (int m = 0; m < 2; m++)
#pragma unroll
                for (int n = 0; n < 8; n++)
                    MMA16816(acc[m][n], a[m][0], b[1][n]);
#pragma unroll
            for (int m = 0; m < 2; m++)
#pragma unroll
                for (int n = 0; n < 8; n++)
                    MMA16816(acc[m][n], a[m][1], b[0][n]);
        }

        __syncthreads();
        if (kc + 3 < NC) load_stage(kc + 3, st);
        CP_COMMIT();
    }

    float* Cz = Cpart + (size_t)zt * T_SEQ * GEN_HIDDEN;
    const int g  = lane >> 2;
    const int tg = lane & 3;
#pragma unroll
    for (int m = 0; m < 2; m++) {
        const int row0 = mt * 128 + warp_m * 32 + m * 16 + g;
#pragma unroll
        for (int n = 0; n < 8; n++) {
            const int col = nt * 128 + warp_n * 64 + n * 8 + tg * 2;
            *(float2*)(Cz + (size_t)row0 * N + col) =
                make_float2(acc[m][n][0], acc[m][n][1]);
            *(float2*)(Cz + (size_t)(row0 + 8) * N + col) =
                make_float2(acc[m][n][2], acc[m][n][3]);
        }
    }
}

// ---------------- split-K reduce + silu + bf16 hi/lo split ------------------
__global__ __launch_bounds__(256) void sk_reduce_kernel(
    const float* __restrict__ part,
    __nv_bfloat16* __restrict__ Chi, __nv_bfloat16* __restrict__ Clo)
{
    const size_t NEL = (size_t)T_SEQ * GEN_HIDDEN;
    size_t i = ((size_t)blockIdx.x * 256 + threadIdx.x) * 4;
    float4 a = *(const float4*)(part + i);
    float4 b = *(const float4*)(part + NEL + i);
    float4 c = *(const float4*)(part + 2 * NEL + i);
    float v0 = a.x + b.x + c.x, v1 = a.y + b.y + c.y;
    float v2 = a.z + b.z + c.z, v3 = a.w + b.w + c.w;
    v0 = v0 / (1.f + __expf(-v0)); v1 = v1 / (1.f + __expf(-v1));
    v2 = v2 / (1.f + __expf(-v2)); v3 = v3 / (1.f + __expf(-v3));
    __nv_bfloat16 h0 = __float2bfloat16(v0), h1 = __float2bfloat16(v1);
    __nv_bfloat16 h2 = __float2bfloat16(v2), h3 = __float2bfloat16(v3);
    __nv_bfloat162 p0 = {h0, h1}, p1 = {h2, h3};
    __nv_bfloat162 q0 = {__float2bfloat16(v0 - __bfloat162float(h0)),
                         __float2bfloat16(v1 - __bfloat162float(h1))};
    __nv_bfloat162 q1 = {__float2bfloat16(v2 - __bfloat162float(h2)),
                         __float2bfloat16(v3 - __bfloat162float(h3))};
    *(__nv_bfloat162*)(Chi + i) = p0; *(__nv_bfloat162*)(Chi + i + 2) = p1;
    *(__nv_bfloat162*)(Clo + i) = q0; *(__nv_bfloat162*)(Clo + i + 2) = q1;
}

// ---------------- split fp32 -> bf16 hi/lo ----------------
__global__ __launch_bounds__(256) void split_kernel(const float* __restrict__ in,
                                                    __nv_bfloat16* __restrict__ oh,
                                                    __nv_bfloat16* __restrict__ ol)
{
    int i = (blockIdx.x * 256 + threadIdx.x) * 4;
    float4 v = *(const float4*)(in + i);
    __nv_bfloat16 h0 = __float2bfloat16(v.x), h1 = __float2bfloat16(v.y);
    __nv_bfloat16 h2 = __float2bfloat16(v.z), h3 = __float2bfloat16(v.w);
    __nv_bfloat162 hh0 = {h0, h1}, hh1 = {h2, h3};
    __nv_bfloat162 ll0 = {__float2bfloat16(v.x - __bfloat162float(h0)),
                          __float2bfloat16(v.y - __bfloat162float(h1))};
    __nv_bfloat162 ll1 = {__float2bfloat16(v.z - __bfloat162float(h2)),
                          __float2bfloat16(v.w - __bfloat162float(h3))};
    *(__nv_bfloat162*)(oh + i) = hh0; *(__nv_bfloat162*)(oh + i + 2) = hh1;
    *(__nv_bfloat162*)(ol + i) = ll0; *(__nv_bfloat162*)(ol + i + 2) = ll1;
}

// ---------------- transpose + split: in[R,C] -> out[C,R] hi/lo --------------
__global__ void transpose_split_kernel(const float* __restrict__ in, int R, int C,
                                       __nv_bfloat16* __restrict__ oh,
                                       __nv_bfloat16* __restrict__ ol)
{
    __shared__ float t[32][33];
    const int c0 = blockIdx.x * 32, r0 = blockIdx.y * 32;
    const int tx = threadIdx.x, ty = threadIdx.y;  // 32 x 8
#pragma unroll
    for (int j = 0; j < 32; j += 8)
        t[ty + j][tx] = in[(size_t)(r0 + ty + j) * C + c0 + tx];
    __syncthreads();
#pragma unroll
    for (int j = 0; j < 32; j += 8) {
        float v = t[tx][ty + j];
        __nv_bfloat16 h = __float2bfloat16(v);
        __nv_bfloat16 lo = __float2bfloat16(v - __bfloat162float(h));
        size_t o = (size_t)(c0 + ty + j) * R + r0 + tx;
        oh[o] = h; ol[o] = lo;
    }
}

// ---------------- Dynamic short conv + silu --------------------------------
__global__ void conv_silu_kernel(const float* __restrict__ u,
                                 const float* __restrict__ kern,
                                 float* __restrict__ uc)
{
    int idx = blockIdx.x * blockDim.x + threadIdx.x;
    int t = idx / CONV_DIM;
    int d = idx - t * CONV_DIM;
    float4 kw = *(const float4*)(kern + (size_t)t * KERN_N + (size_t)d * 4);
    int tb = t - (CONV_W - 1);
    float acc = 0.f;
    if (tb + 0 >= 0) acc = fmaf(u[(size_t)(tb + 0) * CONV_DIM + d], kw.x, acc);
    if (tb + 1 >= 0) acc = fmaf(u[(size_t)(tb + 1) * CONV_DIM + d], kw.y, acc);
    if (tb + 2 >= 0) acc = fmaf(u[(size_t)(tb + 2) * CONV_DIM + d], kw.z, acc);
    acc = fmaf(u[(size_t)t * CONV_DIM + d], kw.w, acc);
    uc[idx] = acc / (1.f + __expf(-acc));
}

// ---------------- beta / g ------------------------------------------------
__global__ __launch_bounds__(128) void ba_kernel(const float* __restrict__ x,
                                                 const float* __restrict__ Wba,
                                                 float* __restrict__ beta,
                                                 float* __restrict__ g)
{
    const int t = blockIdx.x;
    __shared__ float xs[D_MODEL];
    __shared__ float red[128];
    for (int i = threadIdx.x; i < D_MODEL / 4; i += 128)
        *(float4*)&xs[i * 4] = *(const float4*)(x + (size_t)t * D_MODEL + i * 4);
    __syncthreads();
    const int c = threadIdx.x & 31;
    const int seg = threadIdx.x >> 5;
    float acc = 0.f;
    const int k0 = seg * 512;
#pragma unroll 4
    for (int k = k0; k < k0 + 512; k++)
        acc = fmaf(xs[k], Wba[(size_t)k * 32 + c], acc);
    red[threadIdx.x] = acc;
    __syncthreads();
    if (threadIdx.x < 32) {
        float s = red[threadIdx.x] + red[threadIdx.x + 32] +
                  red[threadIdx.x + 64] + red[threadIdx.x + 96];
        if (threadIdx.x < 16) {
            beta[t * NH + threadIdx.x] = 1.f / (1.f + __expf(-s));
        } else {
            float sp = log1pf(__expf(-fabsf(s))) + fmaxf(s, 0.f);
            g[t * NH + (threadIdx.x - 16)] = -sp;
        }
    }
}

// ---------------- l2norm q,k ------------------------------------------------
__global__ __launch_bounds__(256) void norm_kernel(const float* __restrict__ uc,
                                                   float* __restrict__ qn,
                                                   float* __restrict__ kn)
{
    int gw = blockIdx.x * 8 + (threadIdx.x >> 5);
    int lane = threadIdx.x & 31;
    int which = gw >> 15;
    int s = gw & 32767;
    int t = s >> 4;
    int h = s & 15;
    const float* src = uc + (size_t)t * CONV_DIM + which * (NH * DK) + h * DK;
    float* dst = (which ? kn : qn) + ((size_t)t * NH + h) * DK;
    float4 v = *(const float4*)(src + lane * 4);
    float ss = v.x * v.x + v.y * v.y + v.z * v.z + v.w * v.w;
#pragma unroll
    for (int off = 16; off; off >>= 1) ss += __shfl_xor_sync(0xffffffffu, ss, off);
    float r = rsqrtf(ss + 1e-6f);
    if (which == 0) r *= 0.08838834764831845f;
    float4 o = make_float4(v.x * r, v.y * r, v.z * r, v.w * r);
    *(float4*)(dst + lane * 4) = o;
}

// ---------------- Gated delta-rule scan (emits bf16 hi/lo O) ----------------
#define SCH 16
__global__ __launch_bounds__(256) void scan_kernel(
    const float* __restrict__ qn, const float* __restrict__ kn,
    const float* __restrict__ uc, const float* __restrict__ gbuf,
    const float* __restrict__ bbuf,
    __nv_bfloat16* __restrict__ Oh, __nv_bfloat16* __restrict__ Ol)
{
    const int h  = blockIdx.x >> 4;
    const int cg = blockIdx.x & 15;
    const int warp = threadIdx.x >> 5;
    const int lane = threadIdx.x & 31;
    const int col = cg * 8 + warp;

    __shared__ float ks[SCH][128];
    __shared__ float qs[SCH][128];
    __shared__ float gs[SCH];
    __shared__ float bs[SCH];

    float s0 = 0.f, s1 = 0.f, s2 = 0.f, s3 = 0.f;
    const float* vptr = uc + 2 * NH * DK + h * DV + col;

    for (int t0 = 0; t0 < T_SEQ; t0 += SCH) {
        __syncthreads();
        for (int i = threadIdx.x; i < SCH * 32; i += 256) {
            int tt = i >> 5;
            int dd = (i & 31) * 4;
            size_t base = ((size_t)(t0 + tt) * NH + h) * DK + dd;
            *(float4*)&ks[tt][dd] = *(const float4*)(kn + base);
            *(float4*)&qs[tt][dd] = *(const float4*)(qn + base);
        }
        if (threadIdx.x < SCH) {
            gs[threadIdx.x] = gbuf[(t0 + threadIdx.x) * NH + h];
            bs[threadIdx.x] = bbuf[(t0 + threadIdx.x) * NH + h];
        }
        __syncthreads();

#pragma unroll 4
        for (int tt = 0; tt < SCH; tt++) {
            const int t = t0 + tt;
            float dec = __expf(gs[tt]);
            float k0 = ks[tt][lane],      k1 = ks[tt][lane + 32];
            float k2 = ks[tt][lane + 64], k3 = ks[tt][lane + 96];
            s0 *= dec; s1 *= dec; s2 *= dec; s3 *= dec;
            float p = fmaf(k0, s0, fmaf(k1, s1, fmaf(k2, s2, k3 * s3)));
#pragma unroll
            for (int off = 16; off; off >>= 1) p += __shfl_xor_sync(0xffffffffu, p, off);
            float vt = vptr[(size_t)t * CONV_DIM];
            float u = bs[tt] * (vt - p);
            s0 = fmaf(k0, u, s0); s1 = fmaf(k1, u, s1);
            s2 = fmaf(k2, u, s2); s3 = fmaf(k3, u, s3);
            float q0 = qs[tt][lane],      q1 = qs[tt][lane + 32];
            float q2 = qs[tt][lane + 64], q3 = qs[tt][lane + 96];
            float o = fmaf(q0, s0, fmaf(q1, s1, fmaf(q2, s2, q3 * s3)));
#pragma unroll
            for (int off = 16; off; off >>= 1) o += __shfl_xor_sync(0xffffffffu, o, off);
            if (lane == 0) {
                size_t idx = (size_t)t * (NH * DV) + h * DV + col;
                __nv_bfloat16 hb = __float2bfloat16(o);
                Oh[idx] = hb;
                Ol[idx] = __float2bfloat16(o - __bfloat162float(hb));
            }
        }
    }
}

// ---------------- Launch ----------------------------------------------------
extern "C" void kernel_launch(void* const* d_in, const int* in_sizes, int n_in,
                              void* d_out, int out_size)
{
    const float* x      = (const float*)d_in[0];
    const float* W_qkv  = (const float*)d_in[1];
    const float* W_ba   = (const float*)d_in[2];
    const float* gen_w1 = (const float*)d_in[3];
    const float* gen_w2 = (const float*)d_in[4];
    const float* gen_b2 = (const float*)d_in[5];
    const float* W_o    = (const float*)d_in[6];
    float* y = (float*)d_out;

    float *p_u, *p_kern, *p_uc, *p_qn, *p_kn, *p_beta, *p_g, *p_p2;
    cudaGetSymbolAddress((void**)&p_u,    g_u);
    cudaGetSymbolAddress((void**)&p_kern, g_kern);
    cudaGetSymbolAddress((void**)&p_uc,   g_uc);
    cudaGetSymbolAddress((void**)&p_qn,   g_qn);
    cudaGetSymbolAddress((void**)&p_kn,   g_kn);
    cudaGetSymbolAddress((void**)&p_beta, g_beta);
    cudaGetSymbolAddress((void**)&p_g,    g_g);
    cudaGetSymbolAddress((void**)&p_p2,   g_p2);

    __nv_bfloat16 *xh, *xl, *uh, *ul, *hh, *hl, *oh, *ol;
    __nv_bfloat16 *wqh, *wql, *w1h, *w1l, *w2h, *w2l, *woh, *wol;
    cudaGetSymbolAddress((void**)&xh, g_xh);   cudaGetSymbolAddress((void**)&xl, g_xl);
    cudaGetSymbolAddress((void**)&uh, g_uh);   cudaGetSymbolAddress((void**)&ul, g_ul);
    cudaGetSymbolAddress((void**)&hh, g_hh);   cudaGetSymbolAddress((void**)&hl, g_hl);
    cudaGetSymbolAddress((void**)&oh, g_oh);   cudaGetSymbolAddress((void**)&ol, g_ol);
    cudaGetSymbolAddress((void**)&wqh, g_wqh); cudaGetSymbolAddress((void**)&wql, g_wql);
    cudaGetSymbolAddress((void**)&w1h, g_w1h); cudaGetSymbolAddress((void**)&w1l, g_w1l);
    cudaGetSymbolAddress((void**)&w2h, g_w2h); cudaGetSymbolAddress((void**)&w2l, g_w2l);
    cudaGetSymbolAddress((void**)&woh, g_woh); cudaGetSymbolAddress((void**)&wol, g_wol);

    cudaFuncSetAttribute(mm_gemm_big, cudaFuncAttributeMaxDynamicSharedMemorySize,
                         BIG_SMEM);
    cudaFuncSetAttribute(mm_gemm_sk, cudaFuncAttributeMaxDynamicSharedMemorySize,
                         SK_SMEM);

    // Lazily created side streams/events (first call is the uncaptured
    // correctness run). Non-blocking so legacy-stream implicit sync doesn't
    // serialize them; ordering is via explicit events (capture-legal fork/join).
    static cudaStream_t s1 = nullptr, s2 = nullptr;
    static cudaEvent_t e_fork = nullptr, e_split = nullptr, e_side = nullptr;
    if (s1 == nullptr) {
        cudaStreamCreateWithFlags(&s1, cudaStreamNonBlocking);
        cudaStreamCreateWithFlags(&s2, cudaStreamNonBlocking);
        cudaEventCreateWithFlags(&e_fork,  cudaEventDisableTiming);
        cudaEventCreateWithFlags(&e_split, cudaEventDisableTiming);
        cudaEventCreateWithFlags(&e_side,  cudaEventDisableTiming);
    }

    dim3 tb(32, 8);

    // ---- fork: side streams branch off the capture-origin stream ----
    cudaEventRecord(e_fork, 0);
    cudaStreamWaitEvent(s1, e_fork, 0);
    cudaStreamWaitEvent(s2, e_fork, 0);

    // s1: split x (needed by GEMM1)
    split_kernel<<<(T_SEQ * D_MODEL) / 1024, 256, 0, s1>>>(x, xh, xl);
    cudaEventRecord(e_split, s1);

    // s2: off-critical-path prep (needed at GEMM2/GEMM3/GEMM4/scan)
    transpose_split_kernel<<<dim3(GEN_HIDDEN / 32, CONV_DIM / 32), tb, 0, s2>>>(
        gen_w1, CONV_DIM, GEN_HIDDEN, w1h, w1l);
    transpose_split_kernel<<<dim3(KERN_N / 32, GEN_HIDDEN / 32), tb, 0, s2>>>(
        gen_w2, GEN_HIDDEN, KERN_N, w2h, w2l);
    transpose_split_kernel<<<dim3(D_MODEL / 32, D_MODEL / 32), tb, 0, s2>>>(
        W_o, D_MODEL, D_MODEL, woh, wol);
    ba_kernel<<<T_SEQ, 128, 0, s2>>>(x, W_ba, p_beta, p_g);
    cudaEventRecord(e_side, s2);

    // main stream: W_qkv transpose runs concurrently with split_x
    transpose_split_kernel<<<dim3(CONV_DIM / 32, D_MODEL / 32), tb>>>(
        W_qkv, D_MODEL, CONV_DIM, wqh, wql);

    // join split before GEMM1
    cudaStreamWaitEvent(0, e_split, 0);

    // 1) u = x @ W_qkv   (fp32 u for conv + fused bf16 hi/lo for GEMM2)
    mm_gemm_big<<<dim3(T_SEQ / 128, CONV_DIM / 256), 256, BIG_SMEM>>>(
        xh, xl, wqh, wql, p_u, CONV_DIM, D_MODEL, 0, nullptr, uh, ul);

    // join side-prep before GEMM2 (covers w1/w2/wo/ba; s2 ran under GEMM1)
    cudaStreamWaitEvent(0, e_side, 0);

    // 2) h = silu(u @ gen_w1)  split-K=3 + reduce
    mm_gemm_sk<<<dim3(T_SEQ / 128, GEN_HIDDEN / 128, SK), 256, SK_SMEM>>>(
        uh, ul, w1h, w1l, p_p2, GEN_HIDDEN, CONV_DIM);
    sk_reduce_kernel<<<(T_SEQ * GEN_HIDDEN) / 1024, 256>>>(p_p2, hh, hl);

    // 3) kern = h @ gen_w2 + b2
    mm_gemm_big<<<dim3(T_SEQ / 128, KERN_N / 256), 256, BIG_SMEM>>>(
        hh, hl, w2h, w2l, p_kern, KERN_N, GEN_HIDDEN, 2, gen_b2,
        nullptr, nullptr);

    // 4) conv + silu
    conv_silu_kernel<<<(T_SEQ * CONV_DIM) / 256, 256>>>(p_u, p_kern, p_uc);
    // 5) l2norm
    norm_kernel<<<(T_SEQ * NH * 2) / 8, 256>>>(p_uc, p_qn, p_kn);
    // 6) scan (emits bf16 hi/lo O directly)
    scan_kernel<<<NH * 16, 256>>>(p_qn, p_kn, p_uc, p_g, p_beta, oh, ol);

    // 7) y = O @ W_o
    mm_gemm_big<<<dim3(T_SEQ / 128, D_MODEL / 256), 256, BIG_SMEM>>>(
        oh, ol, woh, wol, y, D_MODEL, NH * DV, 0, nullptr, nullptr, nullptr);
}

// round 12
// speedup vs baseline: 1.3776x; 1.3776x over previous
#include <cuda_runtime.h>
#include <cuda_bf16.h>
#include <cstdint>
#include <cstddef>

// ---------------- Problem constants ----------------
#define T_SEQ 2048
#define D_MODEL 2048
#define NH 16
#define DK 128
#define DV 128
#define CONV_W 4
#define CONV_DIM 6144          // NH*2*DK + NH*DV
#define GEN_HIDDEN 768
#define KERN_N 24576           // CONV_DIM * CONV_W
#define SK 3                   // split-K factor for GEMM2
#define SK_LEN 2048            // K per split (6144/3)

// ---------------- fp32 scratch ----------------
__device__ float g_u   [(size_t)T_SEQ * CONV_DIM];
__device__ float g_kern[(size_t)T_SEQ * KERN_N];
__device__ float g_uc  [(size_t)T_SEQ * CONV_DIM];
__device__ float g_qn  [(size_t)T_SEQ * NH * DK];
__device__ float g_kn  [(size_t)T_SEQ * NH * DK];
__device__ float g_beta[(size_t)T_SEQ * NH];
__device__ float g_g   [(size_t)T_SEQ * NH];
__device__ float g_p2  [(size_t)SK * T_SEQ * GEN_HIDDEN];   // split-K partials

// ---------------- bf16 hi/lo splits ----------------
__device__ __nv_bfloat16 g_xh [(size_t)T_SEQ * D_MODEL];
__device__ __nv_bfloat16 g_xl [(size_t)T_SEQ * D_MODEL];
__device__ __nv_bfloat16 g_uh [(size_t)T_SEQ * CONV_DIM];
__device__ __nv_bfloat16 g_ul [(size_t)T_SEQ * CONV_DIM];
__device__ __nv_bfloat16 g_hh [(size_t)T_SEQ * GEN_HIDDEN];
__device__ __nv_bfloat16 g_hl [(size_t)T_SEQ * GEN_HIDDEN];
__device__ __nv_bfloat16 g_oh [(size_t)T_SEQ * NH * DV];
__device__ __nv_bfloat16 g_ol [(size_t)T_SEQ * NH * DV];
// transposed weights [N, K]
__device__ __nv_bfloat16 g_wqh[(size_t)CONV_DIM * D_MODEL];
__device__ __nv_bfloat16 g_wql[(size_t)CONV_DIM * D_MODEL];
__device__ __nv_bfloat16 g_w1h[(size_t)GEN_HIDDEN * CONV_DIM];
__device__ __nv_bfloat16 g_w1l[(size_t)GEN_HIDDEN * CONV_DIM];
__device__ __nv_bfloat16 g_w2h[(size_t)KERN_N * GEN_HIDDEN];
__device__ __nv_bfloat16 g_w2l[(size_t)KERN_N * GEN_HIDDEN];
__device__ __nv_bfloat16 g_woh[(size_t)D_MODEL * D_MODEL];
__device__ __nv_bfloat16 g_wol[(size_t)D_MODEL * D_MODEL];

// ---------------- PTX helpers ----------------
__device__ __forceinline__ uint32_t smem_u32(const void* p) {
    uint32_t a;
    asm("{ .reg .u64 t; cvta.to.shared.u64 t, %1; cvt.u32.u64 %0, t; }" : "=r"(a) : "l"(p));
    return a;
}

#define SWZ(off) ((off) ^ (((off) >> 3) & 0x70))

#define CP_ASYNC16(dst, src) \
    asm volatile("cp.async.cg.shared.global [%0], [%1], 16;" :: "r"(dst), "l"(src) : "memory")
#define CP_COMMIT() asm volatile("cp.async.commit_group;" ::: "memory")
#define CP_WAIT1()  asm volatile("cp.async.wait_group 1;" ::: "memory")
#define CP_WAIT2()  asm volatile("cp.async.wait_group 2;" ::: "memory")

#define LDSM4(r0, r1, r2, r3, addr) \
    asm volatile("ldmatrix.sync.aligned.m8n8.x4.shared.b16 {%0,%1,%2,%3}, [%4];" \
        : "=r"(r0), "=r"(r1), "=r"(r2), "=r"(r3) : "r"(addr))

#define MMA16816(c, a, b) \
    asm volatile("mma.sync.aligned.m16n8k16.row.col.f32.bf16.bf16.f32 " \
        "{%0,%1,%2,%3}, {%4,%5,%6,%7}, {%8,%9}, {%0,%1,%2,%3};" \
        : "+f"((c)[0]), "+f"((c)[1]), "+f"((c)[2]), "+f"((c)[3]) \
        : "r"((a)[0]), "r"((a)[1]), "r"((a)[2]), "r"((a)[3]), "r"((b)[0]), "r"((b)[1]))

// ============================================================================
// mm_gemm_big: CTA 128(M) x 256(N), BK=64, 2-stage. 8 warps = 2(M) x 4(N),
// warp tile 64x64. bf16x3 compensated, fp32 accumulate.
// epi: 0 none, 1 silu, 2 +bias
// ============================================================================
#define BTILE_A 16384
#define BTILE_B 32768
#define BSTAGE  (2 * BTILE_A + 2 * BTILE_B)   // 96 KB
#define BIG_SMEM (2 * BSTAGE + 1024)

__global__ __launch_bounds__(256) void mm_gemm_big(
    const __nv_bfloat16* __restrict__ Ah, const __nv_bfloat16* __restrict__ Al,
    const __nv_bfloat16* __restrict__ Bh, const __nv_bfloat16* __restrict__ Bl,
    float* __restrict__ C, int N, int K, int epi, const float* __restrict__ bias,
    __nv_bfloat16* __restrict__ Chi, __nv_bfloat16* __restrict__ Clo)
{
    extern __shared__ char smem_raw[];
    const uint32_t sb = (smem_u32(smem_raw) + 1023u) & ~1023u;
    const int tid  = threadIdx.x;
    const int lane = tid & 31;
    const int wid  = tid >> 5;
    const int warp_m = wid & 1;
    const int warp_n = wid >> 1;
    const int mt = blockIdx.x, nt = blockIdx.y;

    const __nv_bfloat16* gpA[2] = { Ah + (size_t)mt * 128 * K,
                                    Al + (size_t)mt * 128 * K };
    const __nv_bfloat16* gpB[2] = { Bh + (size_t)nt * 256 * K,
                                    Bl + (size_t)nt * 256 * K };

    const int NC = K >> 6;
    const int ld_row = tid >> 3;
    const int ld_cc  = tid & 7;

    auto load_stage = [&](int kc, int s) {
        const uint32_t stage = sb + (uint32_t)s * BSTAGE;
        const size_t kOff = (size_t)kc * 64 + ld_cc * 8;
#pragma unroll
        for (int op = 0; op < 2; op++) {
            const __nv_bfloat16* base = gpA[op] + kOff;
#pragma unroll
            for (int i = 0; i < 4; i++) {
                const int row = ld_row + i * 32;
                uint32_t off = (uint32_t)(row * 128 + ld_cc * 16);
                CP_ASYNC16(stage + op * BTILE_A + SWZ(off), base + (size_t)row * K);
            }
        }
#pragma unroll
        for (int op = 0; op < 2; op++) {
            const __nv_bfloat16* base = gpB[op] + kOff;
#pragma unroll
            for (int i = 0; i < 8; i++) {
                const int row = ld_row + i * 32;
                uint32_t off = (uint32_t)(row * 128 + ld_cc * 16);
                CP_ASYNC16(stage + 2 * BTILE_A + op * BTILE_B + SWZ(off),
                           base + (size_t)row * K);
            }
        }
    };

    float acc[4][8][4];
#pragma unroll
    for (int m = 0; m < 4; m++)
#pragma unroll
        for (int n = 0; n < 8; n++)
#pragma unroll
            for (int j = 0; j < 4; j++) acc[m][n][j] = 0.f;

    const uint32_t aRow = (lane & 7) + ((lane >> 3) & 1) * 8;
    const uint32_t aKb  = ((lane >> 4) & 1) * 16;
    const uint32_t bRow = (lane & 7) + ((lane >> 4) & 1) * 8;
    const uint32_t bKb  = ((lane >> 3) & 1) * 16;

    load_stage(0, 0); CP_COMMIT();
    load_stage(1, 1); CP_COMMIT();

    for (int kc = 0; kc < NC; kc++) {
        CP_WAIT1();
        __syncthreads();
        const int st = kc & 1;
        const uint32_t base = sb + (uint32_t)st * BSTAGE;

#pragma unroll
        for (int ks = 0; ks < 4; ks++) {
            uint32_t a[4][2][4];
#pragma unroll
            for (int mf = 0; mf < 4; mf++) {
                uint32_t off = (uint32_t)((warp_m * 64 + mf * 16 + aRow) * 128
                                          + ks * 32 + aKb);
                uint32_t sw = SWZ(off);
                LDSM4(a[mf][0][0], a[mf][0][1], a[mf][0][2], a[mf][0][3], base + sw);
                LDSM4(a[mf][1][0], a[mf][1][1], a[mf][1][2], a[mf][1][3],
                      base + BTILE_A + sw);
            }
            uint32_t b[2][8][2];
#pragma unroll
            for (int jp = 0; jp < 4; jp++) {
                uint32_t off = (uint32_t)((warp_n * 64 + jp * 16 + bRow) * 128
                                          + ks * 32 + bKb);
                uint32_t sw = SWZ(off);
                LDSM4(b[0][2 * jp][0], b[0][2 * jp][1],
                      b[0][2 * jp + 1][0], b[0][2 * jp + 1][1],
                      base + 2 * BTILE_A + sw);
                LDSM4(b[1][2 * jp][0], b[1][2 * jp][1],
                      b[1][2 * jp + 1][0], b[1][2 * jp + 1][1],
                      base + 2 * BTILE_A + BTILE_B + sw);
            }
#pragma unroll
            for (int m = 0; m < 4; m++)
#pragma unroll
                for (int n = 0; n < 8; n++)
                    MMA16816(acc[m][n], a[m][0], b[0][n]);   // hi*hi
#pragma unroll
            for (int m = 0; m < 4; m++)
#pragma unroll
                for (int n = 0; n < 8; n++)
                    MMA16816(acc[m][n], a[m][0], b[1][n]);   // hi*lo
#pragma unroll
            for (int m = 0; m < 4; m++)
#pragma unroll
                for (int n = 0; n < 8; n++)
                    MMA16816(acc[m][n], a[m][1], b[0][n]);   // lo*hi
        }

        __syncthreads();
        if (kc + 2 < NC) load_stage(kc + 2, st);
        CP_COMMIT();
    }

    const int g  = lane >> 2;
    const int tg = lane & 3;
#pragma unroll
    for (int m = 0; m < 4; m++) {
        const int row0 = mt * 128 + warp_m * 64 + m * 16 + g;
#pragma unroll
        for (int n = 0; n < 8; n++) {
            const int col = nt * 256 + warp_n * 64 + n * 8 + tg * 2;
            float v0 = acc[m][n][0], v1 = acc[m][n][1];
            float v2 = acc[m][n][2], v3 = acc[m][n][3];
            if (epi == 1) {
                v0 = v0 / (1.f + __expf(-v0)); v1 = v1 / (1.f + __expf(-v1));
                v2 = v2 / (1.f + __expf(-v2)); v3 = v3 / (1.f + __expf(-v3));
            } else if (epi == 2) {
                float b0 = bias[col], b1 = bias[col + 1];
                v0 += b0; v1 += b1; v2 += b0; v3 += b1;
            }
            const size_t i0 = (size_t)row0 * N + col;
            const size_t i1 = (size_t)(row0 + 8) * N + col;
            if (C) {
                *(float2*)(C + i0) = make_float2(v0, v1);
                *(float2*)(C + i1) = make_float2(v2, v3);
            }
            if (Chi) {
                __nv_bfloat16 h0 = __float2bfloat16(v0), h1 = __float2bfloat16(v1);
                __nv_bfloat16 h2 = __float2bfloat16(v2), h3 = __float2bfloat16(v3);
                __nv_bfloat162 p0 = {h0, h1}, p1 = {h2, h3};
                __nv_bfloat162 q0 = {__float2bfloat16(v0 - __bfloat162float(h0)),
                                     __float2bfloat16(v1 - __bfloat162float(h1))};
                __nv_bfloat162 q1 = {__float2bfloat16(v2 - __bfloat162float(h2)),
                                     __float2bfloat16(v3 - __bfloat162float(h3))};
                *(__nv_bfloat162*)(Chi + i0) = p0;
                *(__nv_bfloat162*)(Chi + i1) = p1;
                *(__nv_bfloat162*)(Clo + i0) = q0;
                *(__nv_bfloat162*)(Clo + i1) = q1;
            }
        }
    }
}

// ============================================================================
// mm_gemm_sk: split-K GEMM2. CTA 128x128, BK=64, 3-stage, 8 warps 32x64.
// ============================================================================
#define TILE_B 16384
#define STAGE_B (4 * TILE_B)
#define SK_SMEM (3 * STAGE_B + 1024)

__global__ __launch_bounds__(256) void mm_gemm_sk(
    const __nv_bfloat16* __restrict__ Ah, const __nv_bfloat16* __restrict__ Al,
    const __nv_bfloat16* __restrict__ Bh, const __nv_bfloat16* __restrict__ Bl,
    float* __restrict__ Cpart, int N, int K)
{
    extern __shared__ char smem_raw[];
    const uint32_t sb = (smem_u32(smem_raw) + 1023u) & ~1023u;
    const int tid  = threadIdx.x;
    const int lane = tid & 31;
    const int wid  = tid >> 5;
    const int warp_m = wid & 3;
    const int warp_n = wid >> 2;
    const int mt = blockIdx.x, nt = blockIdx.y, zt = blockIdx.z;
    const int kbase = zt * SK_LEN;

    const __nv_bfloat16* gp[4] = {
        Ah + (size_t)mt * 128 * K + kbase, Al + (size_t)mt * 128 * K + kbase,
        Bh + (size_t)nt * 128 * K + kbase, Bl + (size_t)nt * 128 * K + kbase };

    const int NC = SK_LEN >> 6;   // 32
    const int ch_row[4] = { (tid + 0) >> 3, (tid + 256) >> 3,
                            (tid + 512) >> 3, (tid + 768) >> 3 };
    const int ch_cc = tid & 7;

    auto load_stage = [&](int kc, int s) {
        const uint32_t stage = sb + (uint32_t)s * STAGE_B;
        const size_t kOff = (size_t)kc * 64 + ch_cc * 8;
#pragma unroll
        for (int op = 0; op < 4; op++) {
            const __nv_bfloat16* base = gp[op] + kOff;
#pragma unroll
            for (int i = 0; i < 4; i++) {
                const int row = ch_row[i];
                uint32_t off = (uint32_t)(row * 128 + ch_cc * 16);
                CP_ASYNC16(stage + op * TILE_B + SWZ(off), base + (size_t)row * K);
            }
        }
    };

    float acc[2][8][4];
#pragma unroll
    for (int m = 0; m < 2; m++)
#pragma unroll
        for (int n = 0; n < 8; n++)
#pragma unroll
            for (int j = 0; j < 4; j++) acc[m][n][j] = 0.f;

    const uint32_t aRow = (lane & 7) + ((lane >> 3) & 1) * 8;
    const uint32_t aKb  = ((lane >> 4) & 1) * 16;
    const uint32_t bRow = (lane & 7) + ((lane >> 4) & 1) * 8;
    const uint32_t bKb  = ((lane >> 3) & 1) * 16;

    load_stage(0, 0); CP_COMMIT();
    load_stage(1, 1); CP_COMMIT();
    load_stage(2, 2); CP_COMMIT();

    for (int kc = 0; kc < NC; kc++) {
        CP_WAIT2();
        __syncthreads();
        const int st = kc % 3;
        const uint32_t base = sb + (uint32_t)st * STAGE_B;

#pragma unroll
        for (int ks = 0; ks < 4; ks++) {
            uint32_t a[2][2][4];
#pragma unroll
            for (int m = 0; m < 2; m++) {
                uint32_t off = (uint32_t)((warp_m * 32 + m * 16 + aRow) * 128
                                          + ks * 32 + aKb);
                uint32_t sw = SWZ(off);
                LDSM4(a[m][0][0], a[m][0][1], a[m][0][2], a[m][0][3], base + sw);
                LDSM4(a[m][1][0], a[m][1][1], a[m][1][2], a[m][1][3],
                      base + TILE_B + sw);
            }
            uint32_t b[2][8][2];
#pragma unroll
            for (int jp = 0; jp < 4; jp++) {
                uint32_t off = (uint32_t)((warp_n * 64 + jp * 16 + bRow) * 128
                                          + ks * 32 + bKb);
                uint32_t sw = SWZ(off);
                LDSM4(b[0][2 * jp][0], b[0][2 * jp][1],
                      b[0][2 * jp + 1][0], b[0][2 * jp + 1][1],
                      base + 2 * TILE_B + sw);
                LDSM4(b[1][2 * jp][0], b[1][2 * jp][1],
                      b[1][2 * jp + 1][0], b[1][2 * jp + 1][1],
                      base + 3 * TILE_B + sw);
            }
#pragma unroll
            for (int m = 0; m < 2; m++)
#pragma unroll
                for (int n = 0; n < 8; n++)
                    MMA16816(acc[m][n], a[m][0], b[0][n]);
#pragma unroll
            for (int m = 0; m < 2; m++)
#pragma unroll
                for (int n = 0; n < 8; n++)
                    MMA16816(acc[m][n], a[m][0], b[1][n]);
#pragma unroll
            for (int m = 0; m < 2; m++)
#pragma unroll
                for (int n = 0; n < 8; n++)
                    MMA16816(acc[m][n], a[m][1], b[0][n]);
        }

        __syncthreads();
        if (kc + 3 < NC) load_stage(kc + 3, st);
        CP_COMMIT();
    }

    float* Cz = Cpart + (size_t)zt * T_SEQ * GEN_HIDDEN;
    const int g  = lane >> 2;
    const int tg = lane & 3;
#pragma unroll
    for (int m = 0; m < 2; m++) {
        const int row0 = mt * 128 + warp_m * 32 + m * 16 + g;
#pragma unroll
        for (int n = 0; n < 8; n++) {
            const int col = nt * 128 + warp_n * 64 + n * 8 + tg * 2;
            *(float2*)(Cz + (size_t)row0 * N + col) =
                make_float2(acc[m][n][0], acc[m][n][1]);
            *(float2*)(Cz + (size_t)(row0 + 8) * N + col) =
                make_float2(acc[m][n][2], acc[m][n][3]);
        }
    }
}

// ---------------- split-K reduce + silu + bf16 hi/lo split ------------------
__global__ __launch_bounds__(256) void sk_reduce_kernel(
    const float* __restrict__ part,
    __nv_bfloat16* __restrict__ Chi, __nv_bfloat16* __restrict__ Clo)
{
    const size_t NEL = (size_t)T_SEQ * GEN_HIDDEN;
    size_t i = ((size_t)blockIdx.x * 256 + threadIdx.x) * 4;
    float4 a = *(const float4*)(part + i);
    float4 b = *(const float4*)(part + NEL + i);
    float4 c = *(const float4*)(part + 2 * NEL + i);
    float v0 = a.x + b.x + c.x, v1 = a.y + b.y + c.y;
    float v2 = a.z + b.z + c.z, v3 = a.w + b.w + c.w;
    v0 = v0 / (1.f + __expf(-v0)); v1 = v1 / (1.f + __expf(-v1));
    v2 = v2 / (1.f + __expf(-v2)); v3 = v3 / (1.f + __expf(-v3));
    __nv_bfloat16 h0 = __float2bfloat16(v0), h1 = __float2bfloat16(v1);
    __nv_bfloat16 h2 = __float2bfloat16(v2), h3 = __float2bfloat16(v3);
    __nv_bfloat162 p0 = {h0, h1}, p1 = {h2, h3};
    __nv_bfloat162 q0 = {__float2bfloat16(v0 - __bfloat162float(h0)),
                         __float2bfloat16(v1 - __bfloat162float(h1))};
    __nv_bfloat162 q1 = {__float2bfloat16(v2 - __bfloat162float(h2)),
                         __float2bfloat16(v3 - __bfloat162float(h3))};
    *(__nv_bfloat162*)(Chi + i) = p0; *(__nv_bfloat162*)(Chi + i + 2) = p1;
    *(__nv_bfloat162*)(Clo + i) = q0; *(__nv_bfloat162*)(Clo + i + 2) = q1;
}

// ---------------- split fp32 -> bf16 hi/lo ----------------
__global__ __launch_bounds__(256) void split_kernel(const float* __restrict__ in,
                                                    __nv_bfloat16* __restrict__ oh,
                                                    __nv_bfloat16* __restrict__ ol)
{
    int i = (blockIdx.x * 256 + threadIdx.x) * 4;
    float4 v = *(const float4*)(in + i);
    __nv_bfloat16 h0 = __float2bfloat16(v.x), h1 = __float2bfloat16(v.y);
    __nv_bfloat16 h2 = __float2bfloat16(v.z), h3 = __float2bfloat16(v.w);
    __nv_bfloat162 hh0 = {h0, h1}, hh1 = {h2, h3};
    __nv_bfloat162 ll0 = {__float2bfloat16(v.x - __bfloat162float(h0)),
                          __float2bfloat16(v.y - __bfloat162float(h1))};
    __nv_bfloat162 ll1 = {__float2bfloat16(v.z - __bfloat162float(h2)),
                          __float2bfloat16(v.w - __bfloat162float(h3))};
    *(__nv_bfloat162*)(oh + i) = hh0; *(__nv_bfloat162*)(oh + i + 2) = hh1;
    *(__nv_bfloat162*)(ol + i) = ll0; *(__nv_bfloat162*)(ol + i + 2) = ll1;
}

// ---------------- transpose + split: in[R,C] -> out[C,R] hi/lo --------------
__global__ void transpose_split_kernel(const float* __restrict__ in, int R, int C,
                                       __nv_bfloat16* __restrict__ oh,
                                       __nv_bfloat16* __restrict__ ol)
{
    __shared__ float t[32][33];
    const int c0 = blockIdx.x * 32, r0 = blockIdx.y * 32;
    const int tx = threadIdx.x, ty = threadIdx.y;  // 32 x 8
#pragma unroll
    for (int j = 0; j < 32; j += 8)
        t[ty + j][tx] = in[(size_t)(r0 + ty + j) * C + c0 + tx];
    __syncthreads();
#pragma unroll
    for (int j = 0; j < 32; j += 8) {
        float v = t[tx][ty + j];
        __nv_bfloat16 h = __float2bfloat16(v);
        __nv_bfloat16 lo = __float2bfloat16(v - __bfloat162float(h));
        size_t o = (size_t)(c0 + ty + j) * R + r0 + tx;
        oh[o] = h; ol[o] = lo;
    }
}

// ---------------- Fused conv + silu + l2norm --------------------------------
// Block = 256 threads = 256 consecutive d's of one timestep t (24 chunks/t).
// Chunks 0..15 are q/k (2 heads per block, 128 dims each): conv+silu, then
// 128-wide l2norm, writing qn/kn directly (uc q/k region never touched).
// Chunks 16..23 are v: conv+silu -> uc.
__global__ __launch_bounds__(256) void conv_norm_kernel(
    const float* __restrict__ u, const float* __restrict__ kern,
    float* __restrict__ uc, float* __restrict__ qn, float* __restrict__ kn)
{
    const int chunks_per_t = CONV_DIM / 256;   // 24
    const int t = blockIdx.x / chunks_per_t;
    const int chunk = blockIdx.x - t * chunks_per_t;
    const int d = chunk * 256 + threadIdx.x;

    float4 kw = *(const float4*)(kern + (size_t)t * KERN_N + (size_t)d * 4);
    int tb = t - (CONV_W - 1);
    float acc = 0.f;
    if (tb + 0 >= 0) acc = fmaf(u[(size_t)(tb + 0) * CONV_DIM + d], kw.x, acc);
    if (tb + 1 >= 0) acc = fmaf(u[(size_t)(tb + 1) * CONV_DIM + d], kw.y, acc);
    if (tb + 2 >= 0) acc = fmaf(u[(size_t)(tb + 2) * CONV_DIM + d], kw.z, acc);
    acc = fmaf(u[(size_t)t * CONV_DIM + d], kw.w, acc);
    float val = acc / (1.f + __expf(-acc));

    if (chunk < 16) {
        // q/k region: l2norm over this thread's 128-dim head
        __shared__ float red[8];
        float ss = val * val;
#pragma unroll
        for (int off = 16; off; off >>= 1)
            ss += __shfl_xor_sync(0xffffffffu, ss, off);
        if ((threadIdx.x & 31) == 0) red[threadIdx.x >> 5] = ss;
        __syncthreads();
        const int grp = threadIdx.x >> 7;   // 0 or 1 (which 128-dim head)
        float tot = red[grp * 4 + 0] + red[grp * 4 + 1]
                  + red[grp * 4 + 2] + red[grp * 4 + 3];
        float r = rsqrtf(tot + 1e-6f);
        if (d < NH * DK) {
            qn[(size_t)t * (NH * DK) + d] = val * r * 0.08838834764831845f;
        } else {
            kn[(size_t)t * (NH * DK) + (d - NH * DK)] = val * r;
        }
    } else {
        // v region: scan reads uc here
        uc[(size_t)t * CONV_DIM + d] = val;
    }
}

// ---------------- beta / g ------------------------------------------------
__global__ __launch_bounds__(128) void ba_kernel(const float* __restrict__ x,
                                                 const float* __restrict__ Wba,
                                                 float* __restrict__ beta,
                                                 float* __restrict__ g)
{
    const int t = blockIdx.x;
    __shared__ float xs[D_MODEL];
    __shared__ float red[128];
    for (int i = threadIdx.x; i < D_MODEL / 4; i += 128)
        *(float4*)&xs[i * 4] = *(const float4*)(x + (size_t)t * D_MODEL + i * 4);
    __syncthreads();
    const int c = threadIdx.x & 31;
    const int seg = threadIdx.x >> 5;
    float acc = 0.f;
    const int k0 = seg * 512;
#pragma unroll 4
    for (int k = k0; k < k0 + 512; k++)
        acc = fmaf(xs[k], Wba[(size_t)k * 32 + c], acc);
    red[threadIdx.x] = acc;
    __syncthreads();
    if (threadIdx.x < 32) {
        float s = red[threadIdx.x] + red[threadIdx.x + 32] +
                  red[threadIdx.x + 64] + red[threadIdx.x + 96];
        if (threadIdx.x < 16) {
            beta[t * NH + threadIdx.x] = 1.f / (1.f + __expf(-s));
        } else {
            float sp = log1pf(__expf(-fabsf(s))) + fmaxf(s, 0.f);
            g[t * NH + (threadIdx.x - 16)] = -sp;
        }
    }
}

// ---------------- Gated delta-rule scan (emits bf16 hi/lo O) ----------------
#define SCH 16
__global__ __launch_bounds__(256) void scan_kernel(
    const float* __restrict__ qn, const float* __restrict__ kn,
    const float* __restrict__ uc, const float* __restrict__ gbuf,
    const float* __restrict__ bbuf,
    __nv_bfloat16* __restrict__ Oh, __nv_bfloat16* __restrict__ Ol)
{
    const int h  = blockIdx.x >> 4;
    const int cg = blockIdx.x & 15;
    const int warp = threadIdx.x >> 5;
    const int lane = threadIdx.x & 31;
    const int col = cg * 8 + warp;

    __shared__ float ks[SCH][128];
    __shared__ float qs[SCH][128];
    __shared__ float gs[SCH];
    __shared__ float bs[SCH];

    float s0 = 0.f, s1 = 0.f, s2 = 0.f, s3 = 0.f;
    const float* vptr = uc + 2 * NH * DK + h * DV + col;

    for (int t0 = 0; t0 < T_SEQ; t0 += SCH) {
        __syncthreads();
        for (int i = threadIdx.x; i < SCH * 32; i += 256) {
            int tt = i >> 5;
            int dd = (i & 31) * 4;
            size_t base = ((size_t)(t0 + tt) * NH + h) * DK + dd;
            *(float4*)&ks[tt][dd] = *(const float4*)(kn + base);
            *(float4*)&qs[tt][dd] = *(const float4*)(qn + base);
        }
        if (threadIdx.x < SCH) {
            gs[threadIdx.x] = gbuf[(t0 + threadIdx.x) * NH + h];
            bs[threadIdx.x] = bbuf[(t0 + threadIdx.x) * NH + h];
        }
        __syncthreads();

#pragma unroll 4
        for (int tt = 0; tt < SCH; tt++) {
            const int t = t0 + tt;
            float dec = __expf(gs[tt]);
            float k0 = ks[tt][lane],      k1 = ks[tt][lane + 32];
            float k2 = ks[tt][lane + 64], k3 = ks[tt][lane + 96];
            s0 *= dec; s1 *= dec; s2 *= dec; s3 *= dec;
            float p = fmaf(k0, s0, fmaf(k1, s1, fmaf(k2, s2, k3 * s3)));
#pragma unroll
            for (int off = 16; off; off >>= 1) p += __shfl_xor_sync(0xffffffffu, p, off);
            float vt = vptr[(size_t)t * CONV_DIM];
            float u = bs[tt] * (vt - p);
            s0 = fmaf(k0, u, s0); s1 = fmaf(k1, u, s1);
            s2 = fmaf(k2, u, s2); s3 = fmaf(k3, u, s3);
            float q0 = qs[tt][lane],      q1 = qs[tt][lane + 32];
            float q2 = qs[tt][lane + 64], q3 = qs[tt][lane + 96];
            float o = fmaf(q0, s0, fmaf(q1, s1, fmaf(q2, s2, q3 * s3)));
#pragma unroll
            for (int off = 16; off; off >>= 1) o += __shfl_xor_sync(0xffffffffu, o, off);
            if (lane == 0) {
                size_t idx = (size_t)t * (NH * DV) + h * DV + col;
                __nv_bfloat16 hb = __float2bfloat16(o);
                Oh[idx] = hb;
                Ol[idx] = __float2bfloat16(o - __bfloat162float(hb));
            }
        }
    }
}

// ---------------- Launch ----------------------------------------------------
extern "C" void kernel_launch(void* const* d_in, const int* in_sizes, int n_in,
                              void* d_out, int out_size)
{
    const float* x      = (const float*)d_in[0];
    const float* W_qkv  = (const float*)d_in[1];
    const float* W_ba   = (const float*)d_in[2];
    const float* gen_w1 = (const float*)d_in[3];
    const float* gen_w2 = (const float*)d_in[4];
    const float* gen_b2 = (const float*)d_in[5];
    const float* W_o    = (const float*)d_in[6];
    float* y = (float*)d_out;

    float *p_u, *p_kern, *p_uc, *p_qn, *p_kn, *p_beta, *p_g, *p_p2;
    cudaGetSymbolAddress((void**)&p_u,    g_u);
    cudaGetSymbolAddress((void**)&p_kern, g_kern);
    cudaGetSymbolAddress((void**)&p_uc,   g_uc);
    cudaGetSymbolAddress((void**)&p_qn,   g_qn);
    cudaGetSymbolAddress((void**)&p_kn,   g_kn);
    cudaGetSymbolAddress((void**)&p_beta, g_beta);
    cudaGetSymbolAddress((void**)&p_g,    g_g);
    cudaGetSymbolAddress((void**)&p_p2,   g_p2);

    __nv_bfloat16 *xh, *xl, *uh, *ul, *hh, *hl, *oh, *ol;
    __nv_bfloat16 *wqh, *wql, *w1h, *w1l, *w2h, *w2l, *woh, *wol;
    cudaGetSymbolAddress((void**)&xh, g_xh);   cudaGetSymbolAddress((void**)&xl, g_xl);
    cudaGetSymbolAddress((void**)&uh, g_uh);   cudaGetSymbolAddress((void**)&ul, g_ul);
    cudaGetSymbolAddress((void**)&hh, g_hh);   cudaGetSymbolAddress((void**)&hl, g_hl);
    cudaGetSymbolAddress((void**)&oh, g_oh);   cudaGetSymbolAddress((void**)&ol, g_ol);
    cudaGetSymbolAddress((void**)&wqh, g_wqh); cudaGetSymbolAddress((void**)&wql, g_wql);
    cudaGetSymbolAddress((void**)&w1h, g_w1h); cudaGetSymbolAddress((void**)&w1l, g_w1l);
    cudaGetSymbolAddress((void**)&w2h, g_w2h); cudaGetSymbolAddress((void**)&w2l, g_w2l);
    cudaGetSymbolAddress((void**)&woh, g_woh); cudaGetSymbolAddress((void**)&wol, g_wol);

    cudaFuncSetAttribute(mm_gemm_big, cudaFuncAttributeMaxDynamicSharedMemorySize,
                         BIG_SMEM);
    cudaFuncSetAttribute(mm_gemm_sk, cudaFuncAttributeMaxDynamicSharedMemorySize,
                         SK_SMEM);

    dim3 tb(32, 8);

    // prep: split x + weight transposes (single stream — concurrency regressed)
    split_kernel<<<(T_SEQ * D_MODEL) / 1024, 256>>>(x, xh, xl);
    transpose_split_kernel<<<dim3(CONV_DIM / 32, D_MODEL / 32), tb>>>(
        W_qkv, D_MODEL, CONV_DIM, wqh, wql);
    transpose_split_kernel<<<dim3(GEN_HIDDEN / 32, CONV_DIM / 32), tb>>>(
        gen_w1, CONV_DIM, GEN_HIDDEN, w1h, w1l);
    transpose_split_kernel<<<dim3(KERN_N / 32, GEN_HIDDEN / 32), tb>>>(
        gen_w2, GEN_HIDDEN, KERN_N, w2h, w2l);
    transpose_split_kernel<<<dim3(D_MODEL / 32, D_MODEL / 32), tb>>>(
        W_o, D_MODEL, D_MODEL, woh, wol);

    // 1) u = x @ W_qkv   (fp32 u for conv + fused bf16 hi/lo for GEMM2)
    mm_gemm_big<<<dim3(T_SEQ / 128, CONV_DIM / 256), 256, BIG_SMEM>>>(
        xh, xl, wqh, wql, p_u, CONV_DIM, D_MODEL, 0, nullptr, uh, ul);

    // 2) h = silu(u @ gen_w1)  split-K=3: grid (16,6,3)=288 CTAs, then reduce
    mm_gemm_sk<<<dim3(T_SEQ / 128, GEN_HIDDEN / 128, SK), 256, SK_SMEM>>>(
        uh, ul, w1h, w1l, p_p2, GEN_HIDDEN, CONV_DIM);
    sk_reduce_kernel<<<(T_SEQ * GEN_HIDDEN) / 1024, 256>>>(p_p2, hh, hl);

    // 3) kern = h @ gen_w2 + b2
    mm_gemm_big<<<dim3(T_SEQ / 128, KERN_N / 256), 256, BIG_SMEM>>>(
        hh, hl, w2h, w2l, p_kern, KERN_N, GEN_HIDDEN, 2, gen_b2,
        nullptr, nullptr);

    // 4) beta, g
    ba_kernel<<<T_SEQ, 128>>>(x, W_ba, p_beta, p_g);
    // 5) fused conv + silu + l2norm (qn/kn direct; uc only for v region)
    conv_norm_kernel<<<T_SEQ * (CONV_DIM / 256), 256>>>(p_u, p_kern, p_uc,
                                                        p_qn, p_kn);
    // 6) scan (emits bf16 hi/lo O directly)
    scan_kernel<<<NH * 16, 256>>>(p_qn, p_kn, p_uc, p_g, p_beta, oh, ol);

    // 7) y = O @ W_o
    mm_gemm_big<<<dim3(T_SEQ / 128, D_MODEL / 256), 256, BIG_SMEM>>>(
        oh, ol, woh, wol, y, D_MODEL, NH * DV, 0, nullptr, nullptr, nullptr);
}

// round 14
// speedup vs baseline: 1.3984x; 1.0151x over previous
#include <cuda_runtime.h>
#include <cuda_bf16.h>
#include <cstdint>
#include <cstddef>

// ---------------- Problem constants ----------------
#define T_SEQ 2048
#define D_MODEL 2048
#define NH 16
#define DK 128
#define DV 128
#define CONV_W 4
#define CONV_DIM 6144          // NH*2*DK + NH*DV
#define GEN_HIDDEN 768
#define KERN_N 24576           // CONV_DIM * CONV_W
#define SK 3                   // split-K factor for GEMM2
#define SK_LEN 2048            // K per split (6144/3)

// ---------------- fp32 scratch ----------------
__device__ float g_kern[(size_t)T_SEQ * KERN_N];
__device__ float g_uc  [(size_t)T_SEQ * CONV_DIM];
__device__ float g_qn  [(size_t)T_SEQ * NH * DK];
__device__ float g_kn  [(size_t)T_SEQ * NH * DK];
__device__ float g_beta[(size_t)T_SEQ * NH];
__device__ float g_g   [(size_t)T_SEQ * NH];
__device__ float g_p2  [(size_t)SK * T_SEQ * GEN_HIDDEN];   // split-K partials

// ---------------- bf16 hi/lo splits ----------------
__device__ __nv_bfloat16 g_xh [(size_t)T_SEQ * D_MODEL];
__device__ __nv_bfloat16 g_xl [(size_t)T_SEQ * D_MODEL];
__device__ __nv_bfloat16 g_uh [(size_t)T_SEQ * CONV_DIM];
__device__ __nv_bfloat16 g_ul [(size_t)T_SEQ * CONV_DIM];
__device__ __nv_bfloat16 g_hh [(size_t)T_SEQ * GEN_HIDDEN];
__device__ __nv_bfloat16 g_hl [(size_t)T_SEQ * GEN_HIDDEN];
__device__ __nv_bfloat16 g_oh [(size_t)T_SEQ * NH * DV];
__device__ __nv_bfloat16 g_ol [(size_t)T_SEQ * NH * DV];
// transposed weights [N, K]
__device__ __nv_bfloat16 g_wqh[(size_t)CONV_DIM * D_MODEL];
__device__ __nv_bfloat16 g_wql[(size_t)CONV_DIM * D_MODEL];
__device__ __nv_bfloat16 g_w1h[(size_t)GEN_HIDDEN * CONV_DIM];
__device__ __nv_bfloat16 g_w1l[(size_t)GEN_HIDDEN * CONV_DIM];
__device__ __nv_bfloat16 g_w2h[(size_t)KERN_N * GEN_HIDDEN];
__device__ __nv_bfloat16 g_w2l[(size_t)KERN_N * GEN_HIDDEN];
__device__ __nv_bfloat16 g_woh[(size_t)D_MODEL * D_MODEL];
__device__ __nv_bfloat16 g_wol[(size_t)D_MODEL * D_MODEL];

// ---------------- PTX helpers ----------------
__device__ __forceinline__ uint32_t smem_u32(const void* p) {
    uint32_t a;
    asm("{ .reg .u64 t; cvta.to.shared.u64 t, %1; cvt.u32.u64 %0, t; }" : "=r"(a) : "l"(p));
    return a;
}

#define SWZ(off) ((off) ^ (((off) >> 3) & 0x70))

#define CP_ASYNC16(dst, src) \
    asm volatile("cp.async.cg.shared.global [%0], [%1], 16;" :: "r"(dst), "l"(src) : "memory")
#define CP_COMMIT() asm volatile("cp.async.commit_group;" ::: "memory")
#define CP_WAIT1()  asm volatile("cp.async.wait_group 1;" ::: "memory")
#define CP_WAIT2()  asm volatile("cp.async.wait_group 2;" ::: "memory")

#define LDSM4(r0, r1, r2, r3, addr) \
    asm volatile("ldmatrix.sync.aligned.m8n8.x4.shared.b16 {%0,%1,%2,%3}, [%4];" \
        : "=r"(r0), "=r"(r1), "=r"(r2), "=r"(r3) : "r"(addr))

#define MMA16816(c, a, b) \
    asm volatile("mma.sync.aligned.m16n8k16.row.col.f32.bf16.bf16.f32 " \
        "{%0,%1,%2,%3}, {%4,%5,%6,%7}, {%8,%9}, {%0,%1,%2,%3};" \
        : "+f"((c)[0]), "+f"((c)[1]), "+f"((c)[2]), "+f"((c)[3]) \
        : "r"((a)[0]), "r"((a)[1]), "r"((a)[2]), "r"((a)[3]), "r"((b)[0]), "r"((b)[1]))

// ============================================================================
// mm_gemm_big: CTA 128(M) x 256(N), BK=64, 2-stage. 8 warps = 2(M) x 4(N),
// warp tile 64x64. bf16x3 compensated, fp32 accumulate.
// epi: 0 none, 1 silu, 2 +bias
// ============================================================================
#define BTILE_A 16384
#define BTILE_B 32768
#define BSTAGE  (2 * BTILE_A + 2 * BTILE_B)   // 96 KB
#define BIG_SMEM (2 * BSTAGE + 1024)

__global__ __launch_bounds__(256) void mm_gemm_big(
    const __nv_bfloat16* __restrict__ Ah, const __nv_bfloat16* __restrict__ Al,
    const __nv_bfloat16* __restrict__ Bh, const __nv_bfloat16* __restrict__ Bl,
    float* __restrict__ C, int N, int K, int epi, const float* __restrict__ bias,
    __nv_bfloat16* __restrict__ Chi, __nv_bfloat16* __restrict__ Clo)
{
    extern __shared__ char smem_raw[];
    const uint32_t sb = (smem_u32(smem_raw) + 1023u) & ~1023u;
    const int tid  = threadIdx.x;
    const int lane = tid & 31;
    const int wid  = tid >> 5;
    const int warp_m = wid & 1;
    const int warp_n = wid >> 1;
    const int mt = blockIdx.x, nt = blockIdx.y;

    const __nv_bfloat16* gpA[2] = { Ah + (size_t)mt * 128 * K,
                                    Al + (size_t)mt * 128 * K };
    const __nv_bfloat16* gpB[2] = { Bh + (size_t)nt * 256 * K,
                                    Bl + (size_t)nt * 256 * K };

    const int NC = K >> 6;
    const int ld_row = tid >> 3;
    const int ld_cc  = tid & 7;

    auto load_stage = [&](int kc, int s) {
        const uint32_t stage = sb + (uint32_t)s * BSTAGE;
        const size_t kOff = (size_t)kc * 64 + ld_cc * 8;
#pragma unroll
        for (int op = 0; op < 2; op++) {
            const __nv_bfloat16* base = gpA[op] + kOff;
#pragma unroll
            for (int i = 0; i < 4; i++) {
                const int row = ld_row + i * 32;
                uint32_t off = (uint32_t)(row * 128 + ld_cc * 16);
                CP_ASYNC16(stage + op * BTILE_A + SWZ(off), base + (size_t)row * K);
            }
        }
#pragma unroll
        for (int op = 0; op < 2; op++) {
            const __nv_bfloat16* base = gpB[op] + kOff;
#pragma unroll
            for (int i = 0; i < 8; i++) {
                const int row = ld_row + i * 32;
                uint32_t off = (uint32_t)(row * 128 + ld_cc * 16);
                CP_ASYNC16(stage + 2 * BTILE_A + op * BTILE_B + SWZ(off),
                           base + (size_t)row * K);
            }
        }
    };

    float acc[4][8][4];
#pragma unroll
    for (int m = 0; m < 4; m++)
#pragma unroll
        for (int n = 0; n < 8; n++)
#pragma unroll
            for (int j = 0; j < 4; j++) acc[m][n][j] = 0.f;

    const uint32_t aRow = (lane & 7) + ((lane >> 3) & 1) * 8;
    const uint32_t aKb  = ((lane >> 4) & 1) * 16;
    const uint32_t bRow = (lane & 7) + ((lane >> 4) & 1) * 8;
    const uint32_t bKb  = ((lane >> 3) & 1) * 16;

    load_stage(0, 0); CP_COMMIT();
    load_stage(1, 1); CP_COMMIT();

    for (int kc = 0; kc < NC; kc++) {
        CP_WAIT1();
        __syncthreads();
        const int st = kc & 1;
        const uint32_t base = sb + (uint32_t)st * BSTAGE;

#pragma unroll
        for (int ks = 0; ks < 4; ks++) {
            uint32_t a[4][2][4];
#pragma unroll
            for (int mf = 0; mf < 4; mf++) {
                uint32_t off = (uint32_t)((warp_m * 64 + mf * 16 + aRow) * 128
                                          + ks * 32 + aKb);
                uint32_t sw = SWZ(off);
                LDSM4(a[mf][0][0], a[mf][0][1], a[mf][0][2], a[mf][0][3], base + sw);
                LDSM4(a[mf][1][0], a[mf][1][1], a[mf][1][2], a[mf][1][3],
                      base + BTILE_A + sw);
            }
            uint32_t b[2][8][2];
#pragma unroll
            for (int jp = 0; jp < 4; jp++) {
                uint32_t off = (uint32_t)((warp_n * 64 + jp * 16 + bRow) * 128
                                          + ks * 32 + bKb);
                uint32_t sw = SWZ(off);
                LDSM4(b[0][2 * jp][0], b[0][2 * jp][1],
                      b[0][2 * jp + 1][0], b[0][2 * jp + 1][1],
                      base + 2 * BTILE_A + sw);
                LDSM4(b[1][2 * jp][0], b[1][2 * jp][1],
                      b[1][2 * jp + 1][0], b[1][2 * jp + 1][1],
                      base + 2 * BTILE_A + BTILE_B + sw);
            }
#pragma unroll
            for (int m = 0; m < 4; m++)
#pragma unroll
                for (int n = 0; n < 8; n++)
                    MMA16816(acc[m][n], a[m][0], b[0][n]);   // hi*hi
#pragma unroll
            for (int m = 0; m < 4; m++)
#pragma unroll
                for (int n = 0; n < 8; n++)
                    MMA16816(acc[m][n], a[m][0], b[1][n]);   // hi*lo
#pragma unroll
            for (int m = 0; m < 4; m++)
#pragma unroll
                for (int n = 0; n < 8; n++)
                    MMA16816(acc[m][n], a[m][1], b[0][n]);   // lo*hi
        }

        __syncthreads();
        if (kc + 2 < NC) load_stage(kc + 2, st);
        CP_COMMIT();
    }

    const int g  = lane >> 2;
    const int tg = lane & 3;
#pragma unroll
    for (int m = 0; m < 4; m++) {
        const int row0 = mt * 128 + warp_m * 64 + m * 16 + g;
#pragma unroll
        for (int n = 0; n < 8; n++) {
            const int col = nt * 256 + warp_n * 64 + n * 8 + tg * 2;
            float v0 = acc[m][n][0], v1 = acc[m][n][1];
            float v2 = acc[m][n][2], v3 = acc[m][n][3];
            if (epi == 1) {
                v0 = v0 / (1.f + __expf(-v0)); v1 = v1 / (1.f + __expf(-v1));
                v2 = v2 / (1.f + __expf(-v2)); v3 = v3 / (1.f + __expf(-v3));
            } else if (epi == 2) {
                float b0 = bias[col], b1 = bias[col + 1];
                v0 += b0; v1 += b1; v2 += b0; v3 += b1;
            }
            const size_t i0 = (size_t)row0 * N + col;
            const size_t i1 = (size_t)(row0 + 8) * N + col;
            if (C) {
                *(float2*)(C + i0) = make_float2(v0, v1);
                *(float2*)(C + i1) = make_float2(v2, v3);
            }
            if (Chi) {
                __nv_bfloat16 h0 = __float2bfloat16(v0), h1 = __float2bfloat16(v1);
                __nv_bfloat16 h2 = __float2bfloat16(v2), h3 = __float2bfloat16(v3);
                __nv_bfloat162 p0 = {h0, h1}, p1 = {h2, h3};
                __nv_bfloat162 q0 = {__float2bfloat16(v0 - __bfloat162float(h0)),
                                     __float2bfloat16(v1 - __bfloat162float(h1))};
                __nv_bfloat162 q1 = {__float2bfloat16(v2 - __bfloat162float(h2)),
                                     __float2bfloat16(v3 - __bfloat162float(h3))};
                *(__nv_bfloat162*)(Chi + i0) = p0;
                *(__nv_bfloat162*)(Chi + i1) = p1;
                *(__nv_bfloat162*)(Clo + i0) = q0;
                *(__nv_bfloat162*)(Clo + i1) = q1;
            }
        }
    }
}

// ============================================================================
// mm_gemm_sk: split-K GEMM2. CTA 128x128, BK=64, 3-stage, 8 warps 32x64.
// ============================================================================
#define TILE_B 16384
#define STAGE_B (4 * TILE_B)
#define SK_SMEM (3 * STAGE_B + 1024)

__global__ __launch_bounds__(256) void mm_gemm_sk(
    const __nv_bfloat16* __restrict__ Ah, const __nv_bfloat16* __restrict__ Al,
    const __nv_bfloat16* __restrict__ Bh, const __nv_bfloat16* __restrict__ Bl,
    float* __restrict__ Cpart, int N, int K)
{
    extern __shared__ char smem_raw[];
    const uint32_t sb = (smem_u32(smem_raw) + 1023u) & ~1023u;
    const int tid  = threadIdx.x;
    const int lane = tid & 31;
    const int wid  = tid >> 5;
    const int warp_m = wid & 3;
    const int warp_n = wid >> 2;
    const int mt = blockIdx.x, nt = blockIdx.y, zt = blockIdx.z;
    const int kbase = zt * SK_LEN;

    const __nv_bfloat16* gp[4] = {
        Ah + (size_t)mt * 128 * K + kbase, Al + (size_t)mt * 128 * K + kbase,
        Bh + (size_t)nt * 128 * K + kbase, Bl + (size_t)nt * 128 * K + kbase };

    const int NC = SK_LEN >> 6;   // 32
    const int ch_row[4] = { (tid + 0) >> 3, (tid + 256) >> 3,
                            (tid + 512) >> 3, (tid + 768) >> 3 };
    const int ch_cc = tid & 7;

    auto load_stage = [&](int kc, int s) {
        const uint32_t stage = sb + (uint32_t)s * STAGE_B;
        const size_t kOff = (size_t)kc * 64 + ch_cc * 8;
#pragma unroll
        for (int op = 0; op < 4; op++) {
            const __nv_bfloat16* base = gp[op] + kOff;
#pragma unroll
            for (int i = 0; i < 4; i++) {
                const int row = ch_row[i];
                uint32_t off = (uint32_t)(row * 128 + ch_cc * 16);
                CP_ASYNC16(stage + op * TILE_B + SWZ(off), base + (size_t)row * K);
            }
        }
    };

    float acc[2][8][4];
#pragma unroll
    for (int m = 0; m < 2; m++)
#pragma unroll
        for (int n = 0; n < 8; n++)
#pragma unroll
            for (int j = 0; j < 4; j++) acc[m][n][j] = 0.f;

    const uint32_t aRow = (lane & 7) + ((lane >> 3) & 1) * 8;
    const uint32_t aKb  = ((lane >> 4) & 1) * 16;
    const uint32_t bRow = (lane & 7) + ((lane >> 4) & 1) * 8;
    const uint32_t bKb  = ((lane >> 3) & 1) * 16;

    load_stage(0, 0); CP_COMMIT();
    load_stage(1, 1); CP_COMMIT();
    load_stage(2, 2); CP_COMMIT();

    for (int kc = 0; kc < NC; kc++) {
        CP_WAIT2();
        __syncthreads();
        const int st = kc % 3;
        const uint32_t base = sb + (uint32_t)st * STAGE_B;

#pragma unroll
        for (int ks = 0; ks < 4; ks++) {
            uint32_t a[2][2][4];
#pragma unroll
            for (int m = 0; m < 2; m++) {
                uint32_t off = (uint32_t)((warp_m * 32 + m * 16 + aRow) * 128
                                          + ks * 32 + aKb);
                uint32_t sw = SWZ(off);
                LDSM4(a[m][0][0], a[m][0][1], a[m][0][2], a[m][0][3], base + sw);
                LDSM4(a[m][1][0], a[m][1][1], a[m][1][2], a[m][1][3],
                      base + TILE_B + sw);
            }
            uint32_t b[2][8][2];
#pragma unroll
            for (int jp = 0; jp < 4; jp++) {
                uint32_t off = (uint32_t)((warp_n * 64 + jp * 16 + bRow) * 128
                                          + ks * 32 + bKb);
                uint32_t sw = SWZ(off);
                LDSM4(b[0][2 * jp][0], b[0][2 * jp][1],
                      b[0][2 * jp + 1][0], b[0][2 * jp + 1][1],
                      base + 2 * TILE_B + sw);
                LDSM4(b[1][2 * jp][0], b[1][2 * jp][1],
                      b[1][2 * jp + 1][0], b[1][2 * jp + 1][1],
                      base + 3 * TILE_B + sw);
            }
#pragma unroll
            for (int m = 0; m < 2; m++)
#pragma unroll
                for (int n = 0; n < 8; n++)
                    MMA16816(acc[m][n], a[m][0], b[0][n]);
#pragma unroll
            for (int m = 0; m < 2; m++)
#pragma unroll
                for (int n = 0; n < 8; n++)
                    MMA16816(acc[m][n], a[m][0], b[1][n]);
#pragma unroll
            for (int m = 0; m < 2; m++)
#pragma unroll
                for (int n = 0; n < 8; n++)
                    MMA16816(acc[m][n], a[m][1], b[0][n]);
        }

        __syncthreads();
        if (kc + 3 < NC) load_stage(kc + 3, st);
        CP_COMMIT();
    }

    float* Cz = Cpart + (size_t)zt * T_SEQ * GEN_HIDDEN;
    const int g  = lane >> 2;
    const int tg = lane & 3;
#pragma unroll
    for (int m = 0; m < 2; m++) {
        const int row0 = mt * 128 + warp_m * 32 + m * 16 + g;
#pragma unroll
        for (int n = 0; n < 8; n++) {
            const int col = nt * 128 + warp_n * 64 + n * 8 + tg * 2;
            *(float2*)(Cz + (size_t)row0 * N + col) =
                make_float2(acc[m][n][0], acc[m][n][1]);
            *(float2*)(Cz + (size_t)(row0 + 8) * N + col) =
                make_float2(acc[m][n][2], acc[m][n][3]);
        }
    }
}

// ---------------- split-K reduce + silu + bf16 hi/lo split ------------------
__global__ __launch_bounds__(256) void sk_reduce_kernel(
    const float* __restrict__ part,
    __nv_bfloat16* __restrict__ Chi, __nv_bfloat16* __restrict__ Clo)
{
    const size_t NEL = (size_t)T_SEQ * GEN_HIDDEN;
    size_t i = ((size_t)blockIdx.x * 256 + threadIdx.x) * 4;
    float4 a = *(const float4*)(part + i);
    float4 b = *(const float4*)(part + NEL + i);
    float4 c = *(const float4*)(part + 2 * NEL + i);
    float v0 = a.x + b.x + c.x, v1 = a.y + b.y + c.y;
    float v2 = a.z + b.z + c.z, v3 = a.w + b.w + c.w;
    v0 = v0 / (1.f + __expf(-v0)); v1 = v1 / (1.f + __expf(-v1));
    v2 = v2 / (1.f + __expf(-v2)); v3 = v3 / (1.f + __expf(-v3));
    __nv_bfloat16 h0 = __float2bfloat16(v0), h1 = __float2bfloat16(v1);
    __nv_bfloat16 h2 = __float2bfloat16(v2), h3 = __float2bfloat16(v3);
    __nv_bfloat162 p0 = {h0, h1}, p1 = {h2, h3};
    __nv_bfloat162 q0 = {__float2bfloat16(v0 - __bfloat162float(h0)),
                         __float2bfloat16(v1 - __bfloat162float(h1))};
    __nv_bfloat162 q1 = {__float2bfloat16(v2 - __bfloat162float(h2)),
                         __float2bfloat16(v3 - __bfloat162float(h3))};
    *(__nv_bfloat162*)(Chi + i) = p0; *(__nv_bfloat162*)(Chi + i + 2) = p1;
    *(__nv_bfloat162*)(Clo + i) = q0; *(__nv_bfloat162*)(Clo + i + 2) = q1;
}

// ---------------- split fp32 -> bf16 hi/lo ----------------
__global__ __launch_bounds__(256) void split_kernel(const float* __restrict__ in,
                                                    __nv_bfloat16* __restrict__ oh,
                                                    __nv_bfloat16* __restrict__ ol)
{
    int i = (blockIdx.x * 256 + threadIdx.x) * 4;
    float4 v = *(const float4*)(in + i);
    __nv_bfloat16 h0 = __float2bfloat16(v.x), h1 = __float2bfloat16(v.y);
    __nv_bfloat16 h2 = __float2bfloat16(v.z), h3 = __float2bfloat16(v.w);
    __nv_bfloat162 hh0 = {h0, h1}, hh1 = {h2, h3};
    __nv_bfloat162 ll0 = {__float2bfloat16(v.x - __bfloat162float(h0)),
                          __float2bfloat16(v.y - __bfloat162float(h1))};
    __nv_bfloat162 ll1 = {__float2bfloat16(v.z - __bfloat162float(h2)),
                          __float2bfloat16(v.w - __bfloat162float(h3))};
    *(__nv_bfloat162*)(oh + i) = hh0; *(__nv_bfloat162*)(oh + i + 2) = hh1;
    *(__nv_bfloat162*)(ol + i) = ll0; *(__nv_bfloat162*)(ol + i + 2) = ll1;
}

// ---------------- transpose + split: in[R,C] -> out[C,R] hi/lo --------------
__global__ void transpose_split_kernel(const float* __restrict__ in, int R, int C,
                                       __nv_bfloat16* __restrict__ oh,
                                       __nv_bfloat16* __restrict__ ol)
{
    __shared__ float t[32][33];
    const int c0 = blockIdx.x * 32, r0 = blockIdx.y * 32;
    const int tx = threadIdx.x, ty = threadIdx.y;  // 32 x 8
#pragma unroll
    for (int j = 0; j < 32; j += 8)
        t[ty + j][tx] = in[(size_t)(r0 + ty + j) * C + c0 + tx];
    __syncthreads();
#pragma unroll
    for (int j = 0; j < 32; j += 8) {
        float v = t[tx][ty + j];
        __nv_bfloat16 h = __float2bfloat16(v);
        __nv_bfloat16 lo = __float2bfloat16(v - __bfloat162float(h));
        size_t o = (size_t)(c0 + ty + j) * R + r0 + tx;
        oh[o] = h; ol[o] = lo;
    }
}

// ---------------- Dynamic short conv + silu (u from bf16 hi/lo) -------------
__global__ void conv_silu_kernel(const __nv_bfloat16* __restrict__ uh,
                                 const __nv_bfloat16* __restrict__ ul,
                                 const float* __restrict__ kern,
                                 float* __restrict__ uc)
{
    int idx = blockIdx.x * blockDim.x + threadIdx.x;
    int t = idx / CONV_DIM;
    int d = idx - t * CONV_DIM;
    float4 kw = *(const float4*)(kern + (size_t)t * KERN_N + (size_t)d * 4);
    int tb = t - (CONV_W - 1);
    float acc = 0.f;
    if (tb + 0 >= 0) {
        size_t j = (size_t)(tb + 0) * CONV_DIM + d;
        acc = fmaf(__bfloat162float(uh[j]) + __bfloat162float(ul[j]), kw.x, acc);
    }
    if (tb + 1 >= 0) {
        size_t j = (size_t)(tb + 1) * CONV_DIM + d;
        acc = fmaf(__bfloat162float(uh[j]) + __bfloat162float(ul[j]), kw.y, acc);
    }
    if (tb + 2 >= 0) {
        size_t j = (size_t)(tb + 2) * CONV_DIM + d;
        acc = fmaf(__bfloat162float(uh[j]) + __bfloat162float(ul[j]), kw.z, acc);
    }
    {
        size_t j = (size_t)t * CONV_DIM + d;
        acc = fmaf(__bfloat162float(uh[j]) + __bfloat162float(ul[j]), kw.w, acc);
    }
    uc[idx] = acc / (1.f + __expf(-acc));
}

// ---------------- beta / g ------------------------------------------------
__global__ __launch_bounds__(128) void ba_kernel(const float* __restrict__ x,
                                                 const float* __restrict__ Wba,
                                                 float* __restrict__ beta,
                                                 float* __restrict__ g)
{
    const int t = blockIdx.x;
    __shared__ float xs[D_MODEL];
    __shared__ float red[128];
    for (int i = threadIdx.x; i < D_MODEL / 4; i += 128)
        *(float4*)&xs[i * 4] = *(const float4*)(x + (size_t)t * D_MODEL + i * 4);
    __syncthreads();
    const int c = threadIdx.x & 31;
    const int seg = threadIdx.x >> 5;
    float acc = 0.f;
    const int k0 = seg * 512;
#pragma unroll 4
    for (int k = k0; k < k0 + 512; k++)
        acc = fmaf(xs[k], Wba[(size_t)k * 32 + c], acc);
    red[threadIdx.x] = acc;
    __syncthreads();
    if (threadIdx.x < 32) {
        float s = red[threadIdx.x] + red[threadIdx.x + 32] +
                  red[threadIdx.x + 64] + red[threadIdx.x + 96];
        if (threadIdx.x < 16) {
            beta[t * NH + threadIdx.x] = 1.f / (1.f + __expf(-s));
        } else {
            float sp = log1pf(__expf(-fabsf(s))) + fmaxf(s, 0.f);
            g[t * NH + (threadIdx.x - 16)] = -sp;
        }
    }
}

// ---------------- l2norm q,k ------------------------------------------------
__global__ __launch_bounds__(256) void norm_kernel(const float* __restrict__ uc,
                                                   float* __restrict__ qn,
                                                   float* __restrict__ kn)
{
    int gw = blockIdx.x * 8 + (threadIdx.x >> 5);
    int lane = threadIdx.x & 31;
    int which = gw >> 15;
    int s = gw & 32767;
    int t = s >> 4;
    int h = s & 15;
    const float* src = uc + (size_t)t * CONV_DIM + which * (NH * DK) + h * DK;
    float* dst = (which ? kn : qn) + ((size_t)t * NH + h) * DK;
    float4 v = *(const float4*)(src + lane * 4);
    float ss = v.x * v.x + v.y * v.y + v.z * v.z + v.w * v.w;
#pragma unroll
    for (int off = 16; off; off >>= 1) ss += __shfl_xor_sync(0xffffffffu, ss, off);
    float r = rsqrtf(ss + 1e-6f);
    if (which == 0) r *= 0.08838834764831845f;
    float4 o = make_float4(v.x * r, v.y * r, v.z * r, v.w * r);
    *(float4*)(dst + lane * 4) = o;
}

// ---------------- Gated delta-rule scan (emits bf16 hi/lo O) ----------------
#define SCH 16
__global__ __launch_bounds__(256) void scan_kernel(
    const float* __restrict__ qn, const float* __restrict__ kn,
    const float* __restrict__ uc, const float* __restrict__ gbuf,
    const float* __restrict__ bbuf,
    __nv_bfloat16* __restrict__ Oh, __nv_bfloat16* __restrict__ Ol)
{
    const int h  = blockIdx.x >> 4;
    const int cg = blockIdx.x & 15;
    const int warp = threadIdx.x >> 5;
    const int lane = threadIdx.x & 31;
    const int col = cg * 8 + warp;

    __shared__ float ks[SCH][128];
    __shared__ float qs[SCH][128];
    __shared__ float gs[SCH];
    __shared__ float bs[SCH];

    float s0 = 0.f, s1 = 0.f, s2 = 0.f, s3 = 0.f;
    const float* vptr = uc + 2 * NH * DK + h * DV + col;

    for (int t0 = 0; t0 < T_SEQ; t0 += SCH) {
        __syncthreads();
        for (int i = threadIdx.x; i < SCH * 32; i += 256) {
            int tt = i >> 5;
            int dd = (i & 31) * 4;
            size_t base = ((size_t)(t0 + tt) * NH + h) * DK + dd;
            *(float4*)&ks[tt][dd] = *(const float4*)(kn + base);
            *(float4*)&qs[tt][dd] = *(const float4*)(qn + base);
        }
        if (threadIdx.x < SCH) {
            gs[threadIdx.x] = gbuf[(t0 + threadIdx.x) * NH + h];
            bs[threadIdx.x] = bbuf[(t0 + threadIdx.x) * NH + h];
        }
        __syncthreads();

#pragma unroll 4
        for (int tt = 0; tt < SCH; tt++) {
            const int t = t0 + tt;
            float dec = __expf(gs[tt]);
            float k0 = ks[tt][lane],      k1 = ks[tt][lane + 32];
            float k2 = ks[tt][lane + 64], k3 = ks[tt][lane + 96];
            s0 *= dec; s1 *= dec; s2 *= dec; s3 *= dec;
            float p = fmaf(k0, s0, fmaf(k1, s1, fmaf(k2, s2, k3 * s3)));
#pragma unroll
            for (int off = 16; off; off >>= 1) p += __shfl_xor_sync(0xffffffffu, p, off);
            float vt = vptr[(size_t)t * CONV_DIM];
            float u = bs[tt] * (vt - p);
            s0 = fmaf(k0, u, s0); s1 = fmaf(k1, u, s1);
            s2 = fmaf(k2, u, s2); s3 = fmaf(k3, u, s3);
            float q0 = qs[tt][lane],      q1 = qs[tt][lane + 32];
            float q2 = qs[tt][lane + 64], q3 = qs[tt][lane + 96];
            float o = fmaf(q0, s0, fmaf(q1, s1, fmaf(q2, s2, q3 * s3)));
#pragma unroll
            for (int off = 16; off; off >>= 1) o += __shfl_xor_sync(0xffffffffu, o, off);
            if (lane == 0) {
                size_t idx = (size_t)t * (NH * DV) + h * DV + col;
                __nv_bfloat16 hb = __float2bfloat16(o);
                Oh[idx] = hb;
                Ol[idx] = __float2bfloat16(o - __bfloat162float(hb));
            }
        }
    }
}

// ---------------- Launch ----------------------------------------------------
extern "C" void kernel_launch(void* const* d_in, const int* in_sizes, int n_in,
                              void* d_out, int out_size)
{
    const float* x      = (const float*)d_in[0];
    const float* W_qkv  = (const float*)d_in[1];
    const float* W_ba   = (const float*)d_in[2];
    const float* gen_w1 = (const float*)d_in[3];
    const float* gen_w2 = (const float*)d_in[4];
    const float* gen_b2 = (const float*)d_in[5];
    const float* W_o    = (const float*)d_in[6];
    float* y = (float*)d_out;

    float *p_kern, *p_uc, *p_qn, *p_kn, *p_beta, *p_g, *p_p2;
    cudaGetSymbolAddress((void**)&p_kern, g_kern);
    cudaGetSymbolAddress((void**)&p_uc,   g_uc);
    cudaGetSymbolAddress((void**)&p_qn,   g_qn);
    cudaGetSymbolAddress((void**)&p_kn,   g_kn);
    cudaGetSymbolAddress((void**)&p_beta, g_beta);
    cudaGetSymbolAddress((void**)&p_g,    g_g);
    cudaGetSymbolAddress((void**)&p_p2,   g_p2);

    __nv_bfloat16 *xh, *xl, *uh, *ul, *hh, *hl, *oh, *ol;
    __nv_bfloat16 *wqh, *wql, *w1h, *w1l, *w2h, *w2l, *woh, *wol;
    cudaGetSymbolAddress((void**)&xh, g_xh);   cudaGetSymbolAddress((void**)&xl, g_xl);
    cudaGetSymbolAddress((void**)&uh, g_uh);   cudaGetSymbolAddress((void**)&ul, g_ul);
    cudaGetSymbolAddress((void**)&hh, g_hh);   cudaGetSymbolAddress((void**)&hl, g_hl);
    cudaGetSymbolAddress((void**)&oh, g_oh);   cudaGetSymbolAddress((void**)&ol, g_ol);
    cudaGetSymbolAddress((void**)&wqh, g_wqh); cudaGetSymbolAddress((void**)&wql, g_wql);
    cudaGetSymbolAddress((void**)&w1h, g_w1h); cudaGetSymbolAddress((void**)&w1l, g_w1l);
    cudaGetSymbolAddress((void**)&w2h, g_w2h); cudaGetSymbolAddress((void**)&w2l, g_w2l);
    cudaGetSymbolAddress((void**)&woh, g_woh); cudaGetSymbolAddress((void**)&wol, g_wol);

    cudaFuncSetAttribute(mm_gemm_big, cudaFuncAttributeMaxDynamicSharedMemorySize,
                         BIG_SMEM);
    cudaFuncSetAttribute(mm_gemm_sk, cudaFuncAttributeMaxDynamicSharedMemorySize,
                         SK_SMEM);

    dim3 tb(32, 8);

    // prep: split x + weight transposes
    split_kernel<<<(T_SEQ * D_MODEL) / 1024, 256>>>(x, xh, xl);
    transpose_split_kernel<<<dim3(CONV_DIM / 32, D_MODEL / 32), tb>>>(
        W_qkv, D_MODEL, CONV_DIM, wqh, wql);
    transpose_split_kernel<<<dim3(GEN_HIDDEN / 32, CONV_DIM / 32), tb>>>(
        gen_w1, CONV_DIM, GEN_HIDDEN, w1h, w1l);
    transpose_split_kernel<<<dim3(KERN_N / 32, GEN_HIDDEN / 32), tb>>>(
        gen_w2, GEN_HIDDEN, KERN_N, w2h, w2l);
    transpose_split_kernel<<<dim3(D_MODEL / 32, D_MODEL / 32), tb>>>(
        W_o, D_MODEL, D_MODEL, woh, wol);

    // 1) u = x @ W_qkv   (bf16 hi/lo ONLY — fp32 u eliminated; conv
    //    reconstructs u = hi + lo, exact to ~2^-16 relative)
    mm_gemm_big<<<dim3(T_SEQ / 128, CONV_DIM / 256), 256, BIG_SMEM>>>(
        xh, xl, wqh, wql, nullptr, CONV_DIM, D_MODEL, 0, nullptr, uh, ul);

    // 2) h = silu(u @ gen_w1)  split-K=3: grid (16,6,3)=288 CTAs, then reduce
    mm_gemm_sk<<<dim3(T_SEQ / 128, GEN_HIDDEN / 128, SK), 256, SK_SMEM>>>(
        uh, ul, w1h, w1l, p_p2, GEN_HIDDEN, CONV_DIM);
    sk_reduce_kernel<<<(T_SEQ * GEN_HIDDEN) / 1024, 256>>>(p_p2, hh, hl);

    // 3) kern = h @ gen_w2 + b2
    mm_gemm_big<<<dim3(T_SEQ / 128, KERN_N / 256), 256, BIG_SMEM>>>(
        hh, hl, w2h, w2l, p_kern, KERN_N, GEN_HIDDEN, 2, gen_b2,
        nullptr, nullptr);

    // 4) conv + silu (u from bf16 hi/lo)
    conv_silu_kernel<<<(T_SEQ * CONV_DIM) / 256, 256>>>(uh, ul, p_kern, p_uc);
    // 5) beta, g
    ba_kernel<<<T_SEQ, 128>>>(x, W_ba, p_beta, p_g);
    // 6) l2norm
    norm_kernel<<<(T_SEQ * NH * 2) / 8, 256>>>(p_uc, p_qn, p_kn);
    // 7) scan (emits bf16 hi/lo O directly)
    scan_kernel<<<NH * 16, 256>>>(p_qn, p_kn, p_uc, p_g, p_beta, oh, ol);

    // 8) y = O @ W_o
    mm_gemm_big<<<dim3(T_SEQ / 128, D_MODEL / 256), 256, BIG_SMEM>>>(
        oh, ol, woh, wol, y, D_MODEL, NH * DV, 0, nullptr, nullptr, nullptr);
}